// round 1
// baseline (speedup 1.0000x reference)
#include <cuda_runtime.h>
#include <cstddef>

#define MUL 128
#define TOT 1152
#define NM  384
#define TN  16
#define TE  16
#define NTHREADS 384
#define XP  1156   // pitch for 1152-wide planar tiles (16B aligned)
#define AP  388    // pitch for 384-wide tiles (16B aligned)
#define MAXN 4096

// Scratch: intermediate node features (planar irrep layout: 9 planes of 128)
__device__ float g_na0[MAXN * TOT];
__device__ float g_na [MAXN * TOT];

__device__ __forceinline__ float silu_f(float x) {
    return x / (1.0f + __expf(-x));
}
__device__ __forceinline__ float ssp_f(float x) {
    // softplus(x) - log(2), numerically stable
    return fmaxf(x, 0.0f) + log1pf(__expf(-fabsf(x))) - 0.69314718055994531f;
}

// merged irrep index j -> planar index p*128+u
__device__ __forceinline__ int merged_to_planar(int j) {
    if (j < 128) return j;
    if (j < 512) { int r = j - 128; int u = r / 3; int c = r - 3 * u; return (1 + c) * 128 + u; }
    int r = j - 512; int u = r / 5; int c = r - 5 * u; return (4 + c) * 128 + u;
}

#define S128 0.08838834764831845f  /* 1/sqrt(128) */

// ---------------------------------------------------------------------------
// Node kernel: na0 = irrep_linear(x, W_inner, b_inner)
//              na  = irrep_linear(norm_gate(x, ng_pre...), W_n, b_n)
// Both stored PLANAR in g_na0 / g_na.
// ---------------------------------------------------------------------------
__global__ void __launch_bounds__(NTHREADS) node_kernel(
    const float* __restrict__ node_attr,
    const float* __restrict__ W_inner, const float* __restrict__ b_inner,
    const float* __restrict__ W_n,     const float* __restrict__ b_n,
    const float* __restrict__ pW1, const float* __restrict__ pb1,
    const float* __restrict__ pW2, const float* __restrict__ pb2,
    int N)
{
    extern __shared__ float sm[];
    float* X = sm;              // TN x XP (planar)
    float* A = X + TN * XP;     // TN x AP
    float* B = A + TN * AP;     // TN x AP
    const int tid = threadIdx.x;
    const int n0 = blockIdx.x * TN;

    // load tile (merged -> planar)
    for (int idx = tid; idx < TN * TOT; idx += NTHREADS) {
        int t = idx / TOT, j = idx - t * TOT;
        int n = n0 + t; if (n >= N) n = N - 1;
        X[t * XP + merged_to_planar(j)] = node_attr[(size_t)n * TOT + j];
    }
    __syncthreads();

    // na0 = irrep_linear(X, W_inner, b_inner) -> g_na0 (planar out, coalesced)
    for (int pos = tid; pos < TOT; pos += NTHREADS) {
        int p = pos >> 7, v = pos & 127;
        int i = (p == 0) ? 0 : (p < 4 ? 1 : 2);
        const float* W = W_inner + i * MUL * MUL;
        float acc[TN];
        #pragma unroll
        for (int t = 0; t < TN; t++) acc[t] = 0.0f;
        const int base = p * 128;
        for (int u = 0; u < 128; u += 4) {
            float w0 = W[u * 128 + v], w1 = W[(u + 1) * 128 + v];
            float w2 = W[(u + 2) * 128 + v], w3 = W[(u + 3) * 128 + v];
            #pragma unroll
            for (int t = 0; t < TN; t++) {
                const float4 xv = *reinterpret_cast<const float4*>(&X[t * XP + base + u]);
                acc[t] += xv.x * w0 + xv.y * w1 + xv.z * w2 + xv.w * w3;
            }
        }
        float bias = (p == 0) ? b_inner[v] : 0.0f;
        #pragma unroll
        for (int t = 0; t < TN; t++) {
            int n = n0 + t;
            if (n < N) g_na0[(size_t)n * TOT + pos] = acc[t] * S128 + bias;
        }
    }

    // f0 -> A  (x0 | |irrep1| | |irrep2|)
    for (int idx = tid; idx < TN * NM; idx += NTHREADS) {
        int t = idx / NM, k = idx - t * NM;
        float val;
        const float* Xt = X + t * XP;
        if (k < 128) val = Xt[k];
        else if (k < 256) {
            int u = k - 128;
            float a0 = Xt[128 + u], a1 = Xt[256 + u], a2 = Xt[384 + u];
            val = sqrtf(a0 * a0 + a1 * a1 + a2 * a2);
        } else {
            int u = k - 256;
            float a0 = Xt[512 + u], a1 = Xt[640 + u], a2 = Xt[768 + u];
            float a3 = Xt[896 + u], a4 = Xt[1024 + u];
            val = sqrtf(a0 * a0 + a1 * a1 + a2 * a2 + a3 * a3 + a4 * a4);
        }
        A[t * AP + k] = val;
    }
    __syncthreads();

    // h = silu(f0 @ pW1 + pb1) -> B
    for (int j = tid; j < NM; j += NTHREADS) {
        float acc[TN];
        float b = pb1[j];
        #pragma unroll
        for (int t = 0; t < TN; t++) acc[t] = b;
        for (int k = 0; k < NM; k += 4) {
            float w0 = pW1[k * NM + j], w1 = pW1[(k + 1) * NM + j];
            float w2 = pW1[(k + 2) * NM + j], w3 = pW1[(k + 3) * NM + j];
            #pragma unroll
            for (int t = 0; t < TN; t++) {
                const float4 xv = *reinterpret_cast<const float4*>(&A[t * AP + k]);
                acc[t] += xv.x * w0 + xv.y * w1 + xv.z * w2 + xv.w * w3;
            }
        }
        #pragma unroll
        for (int t = 0; t < TN; t++) B[t * AP + j] = silu_f(acc[t]);
    }
    __syncthreads();

    // g = h @ pW2 + pb2 -> A
    for (int j = tid; j < NM; j += NTHREADS) {
        float acc[TN];
        float b = pb2[j];
        #pragma unroll
        for (int t = 0; t < TN; t++) acc[t] = b;
        for (int k = 0; k < NM; k += 4) {
            float w0 = pW2[k * NM + j], w1 = pW2[(k + 1) * NM + j];
            float w2 = pW2[(k + 2) * NM + j], w3 = pW2[(k + 3) * NM + j];
            #pragma unroll
            for (int t = 0; t < TN; t++) {
                const float4 xv = *reinterpret_cast<const float4*>(&B[t * AP + k]);
                acc[t] += xv.x * w0 + xv.y * w1 + xv.z * w2 + xv.w * w3;
            }
        }
        #pragma unroll
        for (int t = 0; t < TN; t++) A[t * AP + j] = acc[t];
    }
    __syncthreads();

    // gate X in place
    for (int idx = tid; idx < TN * TOT; idx += NTHREADS) {
        int t = idx / TOT, pos = idx - t * TOT;
        int p = pos >> 7, u = pos & 127;
        if (p == 0)       X[t * XP + pos]  = A[t * AP + u];
        else if (p < 4)   X[t * XP + pos] *= A[t * AP + 128 + u];
        else              X[t * XP + pos] *= A[t * AP + 256 + u];
    }
    __syncthreads();

    // na = irrep_linear(X, W_n, b_n) -> g_na (planar)
    for (int pos = tid; pos < TOT; pos += NTHREADS) {
        int p = pos >> 7, v = pos & 127;
        int i = (p == 0) ? 0 : (p < 4 ? 1 : 2);
        const float* W = W_n + i * MUL * MUL;
        float acc[TN];
        #pragma unroll
        for (int t = 0; t < TN; t++) acc[t] = 0.0f;
        const int base = p * 128;
        for (int u = 0; u < 128; u += 4) {
            float w0 = W[u * 128 + v], w1 = W[(u + 1) * 128 + v];
            float w2 = W[(u + 2) * 128 + v], w3 = W[(u + 3) * 128 + v];
            #pragma unroll
            for (int t = 0; t < TN; t++) {
                const float4 xv = *reinterpret_cast<const float4*>(&X[t * XP + base + u]);
                acc[t] += xv.x * w0 + xv.y * w1 + xv.z * w2 + xv.w * w3;
            }
        }
        float bias = (p == 0) ? b_n[v] : 0.0f;
        #pragma unroll
        for (int t = 0; t < TN; t++) {
            int n = n0 + t;
            if (n < N) g_na[(size_t)n * TOT + pos] = acc[t] * S128 + bias;
        }
    }
}

// ---------------------------------------------------------------------------
// Edge kernel: everything per-edge, fused. One CTA = 16 edges.
// ---------------------------------------------------------------------------
__global__ void __launch_bounds__(NTHREADS) edge_kernel(
    const float* __restrict__ edge_attr,
    const int* __restrict__ dst, const int* __restrict__ src,
    const float* __restrict__ npa,
    const float* __restrict__ ngW1, const float* __restrict__ ngb1,
    const float* __restrict__ ngW2, const float* __restrict__ ngb2,
    const float* __restrict__ W_out, const float* __restrict__ b_out,
    const float* __restrict__ fcEW1, const float* __restrict__ fcEW2,
    const float* __restrict__ fcW1, const float* __restrict__ fcb1,
    const float* __restrict__ fcW2, const float* __restrict__ fcb2,
    float* __restrict__ out, int E)
{
    extern __shared__ float sm[];
    float* NP = sm;                 // TE x XP (planar)
    float* A  = NP + TE * XP;       // TE x AP
    float* B  = A + TE * AP;        // TE x AP
    float* Wt = B + TE * AP;        // TE x 128
    float* Mt = Wt + TE * MUL;      // TE x 8
    int*   SD = (int*)(Mt + TE * 8);
    int*   SS = SD + TE;

    const int tid = threadIdx.x;
    const int e0 = blockIdx.x * TE;

    if (tid < TE) {
        int e = e0 + tid; if (e >= E) e = E - 1;
        SD[tid] = dst[e];
        SS[tid] = src[e];
    }
    __syncthreads();

    // Mt[t][j] = ssp((edge_attr[e] @ fcE_W1)/8)
    for (int idx = tid; idx < TE * 8; idx += NTHREADS) {
        int t = idx >> 3, j = idx & 7;
        int e = e0 + t; if (e >= E) e = E - 1;
        const float* ea = edge_attr + (size_t)e * 64;
        float acc = 0.0f;
        #pragma unroll 8
        for (int a = 0; a < 64; a++) acc += ea[a] * fcEW1[a * 8 + j];
        Mt[t * 8 + j] = ssp_f(acc * 0.125f);
    }

    // s0 -> A   (from g_na0, planar)
    const float is3 = 0.57735026918962576f, is5 = 0.44721359549995794f;
    for (int idx = tid; idx < TE * NM; idx += NTHREADS) {
        int t = idx / NM, k = idx - t * NM;
        const float* nd = g_na0 + (size_t)SD[t] * TOT;
        const float* ns = g_na0 + (size_t)SS[t] * TOT;
        float val;
        if (k < 128) val = 0.5f * (nd[k] + ns[k]);
        else if (k < 256) {
            int u = k - 128;
            val = (nd[128 + u] * ns[128 + u] + nd[256 + u] * ns[256 + u]
                 + nd[384 + u] * ns[384 + u]) * is3;
        } else {
            int u = k - 256;
            val = (nd[512 + u] * ns[512 + u] + nd[640 + u] * ns[640 + u]
                 + nd[768 + u] * ns[768 + u] + nd[896 + u] * ns[896 + u]
                 + nd[1024 + u] * ns[1024 + u]) * is5;
        }
        A[t * AP + k] = val;
    }
    __syncthreads();

    // h1 = silu(s0 @ fc_W1 + fc_b1) -> B (TE x 128)
    if (tid < 256) {
        int v = tid & 127;
        int th0 = (tid >> 7) * 8;
        float acc[8];
        float b = fcb1[v];
        #pragma unroll
        for (int t = 0; t < 8; t++) acc[t] = b;
        for (int k = 0; k < NM; k += 4) {
            float w0 = fcW1[k * MUL + v], w1 = fcW1[(k + 1) * MUL + v];
            float w2 = fcW1[(k + 2) * MUL + v], w3 = fcW1[(k + 3) * MUL + v];
            #pragma unroll
            for (int t = 0; t < 8; t++) {
                const float4 xv = *reinterpret_cast<const float4*>(&A[(th0 + t) * AP + k]);
                acc[t] += xv.x * w0 + xv.y * w1 + xv.z * w2 + xv.w * w3;
            }
        }
        #pragma unroll
        for (int t = 0; t < 8; t++) B[(th0 + t) * AP + v] = silu_f(acc[t]);
    }
    __syncthreads();

    // w = (h1 @ fc_W2 + fc_b2) * we    -> Wt (TE x 128)
    if (tid < 256) {
        int v = tid & 127;
        int th0 = (tid >> 7) * 8;
        float acc[8];
        float b = fcb2[v];
        #pragma unroll
        for (int t = 0; t < 8; t++) acc[t] = b;
        for (int k = 0; k < MUL; k += 4) {
            float w0 = fcW2[k * MUL + v], w1 = fcW2[(k + 1) * MUL + v];
            float w2 = fcW2[(k + 2) * MUL + v], w3 = fcW2[(k + 3) * MUL + v];
            #pragma unroll
            for (int t = 0; t < 8; t++) {
                const float4 xv = *reinterpret_cast<const float4*>(&B[(th0 + t) * AP + k]);
                acc[t] += xv.x * w0 + xv.y * w1 + xv.z * w2 + xv.w * w3;
            }
        }
        #pragma unroll
        for (int t = 0; t < 8; t++) {
            float we = 0.0f;
            #pragma unroll
            for (int j = 0; j < 8; j++) we += Mt[(th0 + t) * 8 + j] * fcEW2[j * MUL + v];
            Wt[(th0 + t) * MUL + v] = acc[t] * we * 0.35355339059327373f; // /sqrt(8)
        }
    }
    __syncthreads();

    // NP[t] = (na[src] + na[dst]) * w_full  (planar, w index = merged_j/9)
    for (int idx = tid; idx < TE * TOT; idx += NTHREADS) {
        int t = idx / TOT, pos = idx - t * TOT;
        int p = pos >> 7, u = pos & 127;
        int j;
        if (p == 0)      j = u;
        else if (p < 4)  j = 128 + u * 3 + (p - 1);
        else             j = 512 + u * 5 + (p - 4);
        int wi = j / 9;
        const float* ns = g_na + (size_t)SS[t] * TOT;
        const float* nd = g_na + (size_t)SD[t] * TOT;
        NP[t * XP + pos] = (ns[pos] + nd[pos]) * Wt[t * MUL + wi];
    }
    __syncthreads();

    // f0' -> A
    for (int idx = tid; idx < TE * NM; idx += NTHREADS) {
        int t = idx / NM, k = idx - t * NM;
        const float* Nt = NP + t * XP;
        float val;
        if (k < 128) val = Nt[k];
        else if (k < 256) {
            int u = k - 128;
            float a0 = Nt[128 + u], a1 = Nt[256 + u], a2 = Nt[384 + u];
            val = sqrtf(a0 * a0 + a1 * a1 + a2 * a2);
        } else {
            int u = k - 256;
            float a0 = Nt[512 + u], a1 = Nt[640 + u], a2 = Nt[768 + u];
            float a3 = Nt[896 + u], a4 = Nt[1024 + u];
            val = sqrtf(a0 * a0 + a1 * a1 + a2 * a2 + a3 * a3 + a4 * a4);
        }
        A[t * AP + k] = val;
    }
    __syncthreads();

    // h = silu(f0' @ ngW1 + ngb1) -> B
    for (int j = tid; j < NM; j += NTHREADS) {
        float acc[TE];
        float b = ngb1[j];
        #pragma unroll
        for (int t = 0; t < TE; t++) acc[t] = b;
        for (int k = 0; k < NM; k += 4) {
            float w0 = ngW1[k * NM + j], w1 = ngW1[(k + 1) * NM + j];
            float w2 = ngW1[(k + 2) * NM + j], w3 = ngW1[(k + 3) * NM + j];
            #pragma unroll
            for (int t = 0; t < TE; t++) {
                const float4 xv = *reinterpret_cast<const float4*>(&A[t * AP + k]);
                acc[t] += xv.x * w0 + xv.y * w1 + xv.z * w2 + xv.w * w3;
            }
        }
        #pragma unroll
        for (int t = 0; t < TE; t++) B[t * AP + j] = silu_f(acc[t]);
    }
    __syncthreads();

    // g = h @ ngW2 + ngb2 -> A
    for (int j = tid; j < NM; j += NTHREADS) {
        float acc[TE];
        float b = ngb2[j];
        #pragma unroll
        for (int t = 0; t < TE; t++) acc[t] = b;
        for (int k = 0; k < NM; k += 4) {
            float w0 = ngW2[k * NM + j], w1 = ngW2[(k + 1) * NM + j];
            float w2 = ngW2[(k + 2) * NM + j], w3 = ngW2[(k + 3) * NM + j];
            #pragma unroll
            for (int t = 0; t < TE; t++) {
                const float4 xv = *reinterpret_cast<const float4*>(&B[t * AP + k]);
                acc[t] += xv.x * w0 + xv.y * w1 + xv.z * w2 + xv.w * w3;
            }
        }
        #pragma unroll
        for (int t = 0; t < TE; t++) A[t * AP + j] = acc[t];
    }
    __syncthreads();

    // gate NP in place
    for (int idx = tid; idx < TE * TOT; idx += NTHREADS) {
        int t = idx / TOT, pos = idx - t * TOT;
        int p = pos >> 7, u = pos & 127;
        if (p == 0)      NP[t * XP + pos]  = A[t * AP + u];
        else if (p < 4)  NP[t * XP + pos] *= A[t * AP + 128 + u];
        else             NP[t * XP + pos] *= A[t * AP + 256 + u];
    }
    __syncthreads();

    // out = irrep_linear(NP, W_out, b_out) + node_pair_attr  (merged writes)
    for (int j = tid; j < TOT; j += NTHREADS) {
        int i, v, p;
        if (j < 128)      { i = 0; v = j; p = 0; }
        else if (j < 512) { int r = j - 128; v = r / 3; int c = r - 3 * v; i = 1; p = 1 + c; }
        else              { int r = j - 512; v = r / 5; int c = r - 5 * v; i = 2; p = 4 + c; }
        const float* W = W_out + i * MUL * MUL;
        float acc[TE];
        #pragma unroll
        for (int t = 0; t < TE; t++) acc[t] = 0.0f;
        const int base = p * 128;
        for (int u = 0; u < 128; u += 4) {
            float w0 = W[u * 128 + v], w1 = W[(u + 1) * 128 + v];
            float w2 = W[(u + 2) * 128 + v], w3 = W[(u + 3) * 128 + v];
            #pragma unroll
            for (int t = 0; t < TE; t++) {
                const float4 xv = *reinterpret_cast<const float4*>(&NP[t * XP + base + u]);
                acc[t] += xv.x * w0 + xv.y * w1 + xv.z * w2 + xv.w * w3;
            }
        }
        float bias = (i == 0) ? b_out[v] : 0.0f;
        #pragma unroll
        for (int t = 0; t < TE; t++) {
            int e = e0 + t;
            if (e < E)
                out[(size_t)e * TOT + j] = acc[t] * S128 + bias + npa[(size_t)e * TOT + j];
        }
    }
}

// ---------------------------------------------------------------------------
extern "C" void kernel_launch(void* const* d_in, const int* in_sizes, int n_in,
                              void* d_out, int out_size) {
    const float* node_attr = (const float*)d_in[0];
    const float* edge_attr = (const float*)d_in[1];
    const int*   dst       = (const int*)d_in[2];
    const int*   src       = (const int*)d_in[3];
    const float* npa       = (const float*)d_in[4];
    const float* W_inner   = (const float*)d_in[5];
    const float* b_inner   = (const float*)d_in[6];
    const float* W_n       = (const float*)d_in[7];
    const float* b_n       = (const float*)d_in[8];
    const float* W_out     = (const float*)d_in[9];
    const float* b_out     = (const float*)d_in[10];
    const float* pW1       = (const float*)d_in[11];
    const float* pb1       = (const float*)d_in[12];
    const float* pW2       = (const float*)d_in[13];
    const float* pb2       = (const float*)d_in[14];
    const float* gW1       = (const float*)d_in[15];
    const float* gb1       = (const float*)d_in[16];
    const float* gW2       = (const float*)d_in[17];
    const float* gb2       = (const float*)d_in[18];
    const float* fcEW1     = (const float*)d_in[19];
    const float* fcEW2     = (const float*)d_in[20];
    const float* fcW1      = (const float*)d_in[21];
    const float* fcb1      = (const float*)d_in[22];
    const float* fcW2      = (const float*)d_in[23];
    const float* fcb2      = (const float*)d_in[24];

    int N = in_sizes[0] / TOT;
    int E = in_sizes[2];

    size_t smem_node = (size_t)(TN * XP + 2 * TN * AP) * sizeof(float);
    size_t smem_edge = (size_t)(TE * XP + 2 * TE * AP + TE * MUL + TE * 8 + 32) * sizeof(float);

    cudaFuncSetAttribute(node_kernel, cudaFuncAttributeMaxDynamicSharedMemorySize, (int)smem_node);
    cudaFuncSetAttribute(edge_kernel, cudaFuncAttributeMaxDynamicSharedMemorySize, (int)smem_edge);

    node_kernel<<<(N + TN - 1) / TN, NTHREADS, smem_node>>>(
        node_attr, W_inner, b_inner, W_n, b_n, pW1, pb1, pW2, pb2, N);

    edge_kernel<<<(E + TE - 1) / TE, NTHREADS, smem_edge>>>(
        edge_attr, dst, src, npa, gW1, gb1, gW2, gb2, W_out, b_out,
        fcEW1, fcEW2, fcW1, fcb1, fcW2, fcb2, (float*)d_out, E);
}

// round 4
// speedup vs baseline: 2.9301x; 2.9301x over previous
#include <cuda_runtime.h>
#include <cuda_bf16.h>
#include <cstdint>
#include <cstddef>

#define MUL 128
#define TOT 1152
#define NM  384
#define MAXN 4096
#define MAXE 65536
#define S128 0.08838834764831845f

// ---------------- scratch ----------------
__device__ float g_na0[MAXN * TOT];
__device__ float g_na [MAXN * TOT];
__device__ float g_s0f[(size_t)MAXE * NM];   // s0, later reused as f0'
__device__ float g_mt [(size_t)MAXE * 8];
__device__ float g_we [(size_t)MAXE * MUL];
__device__ float g_h  [(size_t)MAXE * NM];   // h1 (ld 128), later h (ld 384)
__device__ float g_w  [(size_t)MAXE * MUL];
__device__ float g_np [(size_t)MAXE * TOT];
__device__ float g_g  [(size_t)MAXE * NM];

// prepped weights (bf16 hi/lo, transposed [n][k] + xor-swizzled 16B units)
#define OFF_FCW1 0
#define OFF_FCW2 49152
#define OFF_NGW1 65536
#define OFF_NGW2 212992
#define OFF_WOUT 360448
#define PW_TOTAL 409600
__device__ __nv_bfloat16 g_pw_hi[PW_TOTAL];
__device__ __nv_bfloat16 g_pw_lo[PW_TOTAL];

__device__ __forceinline__ uint32_t smem_to_u32(const void* p) {
    uint32_t a;
    asm("{ .reg .u64 t; cvta.to.shared.u64 t, %1; cvt.u32.u64 %0, t; }" : "=r"(a) : "l"(p));
    return a;
}
__device__ __forceinline__ float silu_f(float x) { return x / (1.0f + __expf(-x)); }
__device__ __forceinline__ float ssp_f(float x) {
    return fmaxf(x, 0.0f) + log1pf(__expf(-fabsf(x))) - 0.69314718055994531f;
}

// 16B-unit index inside a 128x128 bf16 tile (row-major 256B rows, xor swizzle)
__device__ __forceinline__ int sw_unit(int row, int u) {
    return row * 16 + (u ^ (row & 7));
}

__device__ __forceinline__ void ldmat_x4(uint32_t* r, uint32_t addr) {
    asm volatile("ldmatrix.sync.aligned.m8n8.x4.shared.b16 {%0,%1,%2,%3}, [%4];"
        : "=r"(r[0]), "=r"(r[1]), "=r"(r[2]), "=r"(r[3]) : "r"(addr));
}
__device__ __forceinline__ void mma_bf16(float* c, const uint32_t* a, uint32_t b0, uint32_t b1) {
    asm volatile("mma.sync.aligned.m16n8k16.row.col.f32.bf16.bf16.f32 "
        "{%0,%1,%2,%3}, {%4,%5,%6,%7}, {%8,%9}, {%0,%1,%2,%3};"
        : "+f"(c[0]), "+f"(c[1]), "+f"(c[2]), "+f"(c[3])
        : "r"(a[0]), "r"(a[1]), "r"(a[2]), "r"(a[3]), "r"(b0), "r"(b1));
}

// ---------------- weight prep ----------------
// src: fp32 [K x N] row-major -> per (nt,kc) 128x128 tile, stored B[n][k] swizzled
__global__ void prep_weight(const float* __restrict__ W, int K, int N, int dstoff) {
    int idx = blockIdx.x * blockDim.x + threadIdx.x;
    if (idx >= K * N) return;
    int kg = idx / N, ng = idx - kg * N;
    float x = W[idx];
    __nv_bfloat16 h = __float2bfloat16(x);
    __nv_bfloat16 l = __float2bfloat16(x - __bfloat162float(h));
    int kchunks = K >> 7;
    int nt = ng >> 7, n = ng & 127, kc = kg >> 7, k = kg & 127;
    int blk = nt * kchunks + kc;
    int e = blk * 16384 + sw_unit(n, k >> 3) * 8 + (k & 7) + dstoff;
    g_pw_hi[e] = h;
    g_pw_lo[e] = l;
}

// ---------------- node kernel (planar outputs) ----------------
#define TN 16
#define NTHREADS 384
#define XP 1156
#define AP 388
__device__ __forceinline__ int merged_to_planar(int j) {
    if (j < 128) return j;
    if (j < 512) { int r = j - 128; int u = r / 3; int c = r - 3 * u; return (1 + c) * 128 + u; }
    int r = j - 512; int u = r / 5; int c = r - 5 * u; return (4 + c) * 128 + u;
}
__global__ void __launch_bounds__(NTHREADS) node_kernel(
    const float* __restrict__ node_attr,
    const float* __restrict__ W_inner, const float* __restrict__ b_inner,
    const float* __restrict__ W_n,     const float* __restrict__ b_n,
    const float* __restrict__ pW1, const float* __restrict__ pb1,
    const float* __restrict__ pW2, const float* __restrict__ pb2,
    int N)
{
    extern __shared__ float sm[];
    float* X = sm;
    float* A = X + TN * XP;
    float* B = A + TN * AP;
    const int tid = threadIdx.x;
    const int n0 = blockIdx.x * TN;

    for (int idx = tid; idx < TN * TOT; idx += NTHREADS) {
        int t = idx / TOT, j = idx - t * TOT;
        int n = n0 + t; if (n >= N) n = N - 1;
        X[t * XP + merged_to_planar(j)] = node_attr[(size_t)n * TOT + j];
    }
    __syncthreads();

    for (int pos = tid; pos < TOT; pos += NTHREADS) {
        int p = pos >> 7, v = pos & 127;
        int i = (p == 0) ? 0 : (p < 4 ? 1 : 2);
        const float* W = W_inner + i * MUL * MUL;
        float acc[TN];
        #pragma unroll
        for (int t = 0; t < TN; t++) acc[t] = 0.0f;
        const int base = p * 128;
        for (int u = 0; u < 128; u += 4) {
            float w0 = W[u * 128 + v], w1 = W[(u + 1) * 128 + v];
            float w2 = W[(u + 2) * 128 + v], w3 = W[(u + 3) * 128 + v];
            #pragma unroll
            for (int t = 0; t < TN; t++) {
                const float4 xv = *reinterpret_cast<const float4*>(&X[t * XP + base + u]);
                acc[t] += xv.x * w0 + xv.y * w1 + xv.z * w2 + xv.w * w3;
            }
        }
        float bias = (p == 0) ? b_inner[v] : 0.0f;
        #pragma unroll
        for (int t = 0; t < TN; t++) {
            int n = n0 + t;
            if (n < N) g_na0[(size_t)n * TOT + pos] = acc[t] * S128 + bias;
        }
    }

    for (int idx = tid; idx < TN * NM; idx += NTHREADS) {
        int t = idx / NM, k = idx - t * NM;
        float val;
        const float* Xt = X + t * XP;
        if (k < 128) val = Xt[k];
        else if (k < 256) {
            int u = k - 128;
            float a0 = Xt[128 + u], a1 = Xt[256 + u], a2 = Xt[384 + u];
            val = sqrtf(a0 * a0 + a1 * a1 + a2 * a2);
        } else {
            int u = k - 256;
            float a0 = Xt[512 + u], a1 = Xt[640 + u], a2 = Xt[768 + u];
            float a3 = Xt[896 + u], a4 = Xt[1024 + u];
            val = sqrtf(a0 * a0 + a1 * a1 + a2 * a2 + a3 * a3 + a4 * a4);
        }
        A[t * AP + k] = val;
    }
    __syncthreads();

    for (int j = tid; j < NM; j += NTHREADS) {
        float acc[TN];
        float b = pb1[j];
        #pragma unroll
        for (int t = 0; t < TN; t++) acc[t] = b;
        for (int k = 0; k < NM; k += 4) {
            float w0 = pW1[k * NM + j], w1 = pW1[(k + 1) * NM + j];
            float w2 = pW1[(k + 2) * NM + j], w3 = pW1[(k + 3) * NM + j];
            #pragma unroll
            for (int t = 0; t < TN; t++) {
                const float4 xv = *reinterpret_cast<const float4*>(&A[t * AP + k]);
                acc[t] += xv.x * w0 + xv.y * w1 + xv.z * w2 + xv.w * w3;
            }
        }
        #pragma unroll
        for (int t = 0; t < TN; t++) B[t * AP + j] = silu_f(acc[t]);
    }
    __syncthreads();

    for (int j = tid; j < NM; j += NTHREADS) {
        float acc[TN];
        float b = pb2[j];
        #pragma unroll
        for (int t = 0; t < TN; t++) acc[t] = b;
        for (int k = 0; k < NM; k += 4) {
            float w0 = pW2[k * NM + j], w1 = pW2[(k + 1) * NM + j];
            float w2 = pW2[(k + 2) * NM + j], w3 = pW2[(k + 3) * NM + j];
            #pragma unroll
            for (int t = 0; t < TN; t++) {
                const float4 xv = *reinterpret_cast<const float4*>(&B[t * AP + k]);
                acc[t] += xv.x * w0 + xv.y * w1 + xv.z * w2 + xv.w * w3;
            }
        }
        #pragma unroll
        for (int t = 0; t < TN; t++) A[t * AP + j] = acc[t];
    }
    __syncthreads();

    for (int idx = tid; idx < TN * TOT; idx += NTHREADS) {
        int t = idx / TOT, pos = idx - t * TOT;
        int p = pos >> 7, u = pos & 127;
        if (p == 0)       X[t * XP + pos]  = A[t * AP + u];
        else if (p < 4)   X[t * XP + pos] *= A[t * AP + 128 + u];
        else              X[t * XP + pos] *= A[t * AP + 256 + u];
    }
    __syncthreads();

    for (int pos = tid; pos < TOT; pos += NTHREADS) {
        int p = pos >> 7, v = pos & 127;
        int i = (p == 0) ? 0 : (p < 4 ? 1 : 2);
        const float* W = W_n + i * MUL * MUL;
        float acc[TN];
        #pragma unroll
        for (int t = 0; t < TN; t++) acc[t] = 0.0f;
        const int base = p * 128;
        for (int u = 0; u < 128; u += 4) {
            float w0 = W[u * 128 + v], w1 = W[(u + 1) * 128 + v];
            float w2 = W[(u + 2) * 128 + v], w3 = W[(u + 3) * 128 + v];
            #pragma unroll
            for (int t = 0; t < TN; t++) {
                const float4 xv = *reinterpret_cast<const float4*>(&X[t * XP + base + u]);
                acc[t] += xv.x * w0 + xv.y * w1 + xv.z * w2 + xv.w * w3;
            }
        }
        float bias = (p == 0) ? b_n[v] : 0.0f;
        #pragma unroll
        for (int t = 0; t < TN; t++) {
            int n = n0 + t;
            if (n < N) g_na[(size_t)n * TOT + pos] = acc[t] * S128 + bias;
        }
    }
}

// ---------------- elementwise kernels ----------------
__global__ void k_mt(const float* __restrict__ ea, const float* __restrict__ W1, int E) {
    int idx = blockIdx.x * blockDim.x + threadIdx.x;
    if (idx >= E * 8) return;
    int e = idx >> 3, j = idx & 7;
    const float* a = ea + (size_t)e * 64;
    float acc = 0.0f;
    #pragma unroll 16
    for (int i = 0; i < 64; i++) acc += a[i] * W1[i * 8 + j];
    g_mt[idx] = ssp_f(acc * 0.125f);
}

__global__ void k_we(const float* __restrict__ W2, int E) {
    int idx = blockIdx.x * blockDim.x + threadIdx.x;
    if (idx >= E * MUL) return;
    int e = idx >> 7, n = idx & 127;
    const float* m = g_mt + (size_t)e * 8;
    float acc = 0.0f;
    #pragma unroll
    for (int j = 0; j < 8; j++) acc += m[j] * W2[j * MUL + n];
    g_we[idx] = acc * 0.35355339059327373f;
}

__global__ void k_s0(const int* __restrict__ dst, const int* __restrict__ src, int E) {
    int idx = blockIdx.x * blockDim.x + threadIdx.x;
    if (idx >= E * NM) return;
    int e = idx / NM, k = idx - e * NM;
    const float* nd = g_na0 + (size_t)dst[e] * TOT;
    const float* ns = g_na0 + (size_t)src[e] * TOT;
    float val;
    if (k < 128) val = 0.5f * (nd[k] + ns[k]);
    else if (k < 256) {
        int u = k - 128;
        val = (nd[128 + u] * ns[128 + u] + nd[256 + u] * ns[256 + u]
             + nd[384 + u] * ns[384 + u]) * 0.57735026918962576f;
    } else {
        int u = k - 256;
        val = (nd[512 + u] * ns[512 + u] + nd[640 + u] * ns[640 + u]
             + nd[768 + u] * ns[768 + u] + nd[896 + u] * ns[896 + u]
             + nd[1024 + u] * ns[1024 + u]) * 0.44721359549995794f;
    }
    g_s0f[idx] = val;
}

__global__ void k_npf(const int* __restrict__ dst, const int* __restrict__ src, int E) {
    int idx = blockIdx.x * blockDim.x + threadIdx.x;
    if (idx >= E * MUL) return;
    int e = idx >> 7, u = idx & 127;
    const float* ns = g_na + (size_t)src[e] * TOT;
    const float* nd = g_na + (size_t)dst[e] * TOT;
    const float* w = g_w + (size_t)e * MUL;
    float np[9];
    np[0] = (ns[u] + nd[u]) * w[u / 9];
    #pragma unroll
    for (int p = 1; p < 4; p++) {
        int j = 128 + u * 3 + (p - 1);
        np[p] = (ns[p * 128 + u] + nd[p * 128 + u]) * w[j / 9];
    }
    #pragma unroll
    for (int p = 4; p < 9; p++) {
        int j = 512 + u * 5 + (p - 4);
        np[p] = (ns[p * 128 + u] + nd[p * 128 + u]) * w[j / 9];
    }
    float* npo = g_np + (size_t)e * TOT;
    #pragma unroll
    for (int p = 0; p < 9; p++) npo[p * 128 + u] = np[p];
    float* f = g_s0f + (size_t)e * NM;
    f[u] = np[0];
    f[128 + u] = sqrtf(np[1] * np[1] + np[2] * np[2] + np[3] * np[3]);
    f[256 + u] = sqrtf(np[4] * np[4] + np[5] * np[5] + np[6] * np[6]
                     + np[7] * np[7] + np[8] * np[8]);
}

// ---------------- mma.sync GEMM ----------------
// CTA: 128 edges x 128 cols, 8 warps (4x2), warp tile 32x64.
// split-bf16 3 passes: D = AhiBhi + AhiBlo + AloBhi (fp32 reg accum).
#define GT 256
#define SM_AHI 0
#define SM_ALO 32768
#define SM_BHI 65536
#define SM_BLO 98304
#define SM_TOTAL 131072

// mode_a: 0 plain A[e*lda + k] ; 1 gated planar np (plane = blockIdx.y)
// mode_ep: 0 +bias ; 1 silu(+bias) ; 2 (acc+bias)*mul ; 3 irrep-out scatter (+npa)
__global__ void __launch_bounds__(GT, 1) gemm_kernel(
    const float* __restrict__ A, int lda, int kchunks,
    const __nv_bfloat16* __restrict__ Bhi, const __nv_bfloat16* __restrict__ Blo,
    float* __restrict__ OUT, int ldo,
    const float* __restrict__ bias,
    const float* __restrict__ mul,
    const float* __restrict__ gate,
    const float* __restrict__ npa,
    int mode_a, int mode_ep, int E)
{
    extern __shared__ char smg[];
    uint32_t smb = smem_to_u32(smg);
    const int tid = threadIdx.x;
    const int wid = tid >> 5;
    const int lane = tid & 31;
    const int m0 = blockIdx.x * 128;
    const int by = blockIdx.y;
    const int plane = (mode_a == 1) ? by : 0;
    const int ntb = (mode_a == 1) ? 0 : by;   // output col-block

    const int wm0 = (wid & 3) * 32;
    const int wn0 = (wid >> 2) * 64;

    float acc[2][8][4];
    #pragma unroll
    for (int i = 0; i < 2; i++)
        #pragma unroll
        for (int j = 0; j < 8; j++)
            #pragma unroll
            for (int q = 0; q < 4; q++) acc[i][j][q] = 0.0f;

    for (int kc = 0; kc < kchunks; kc++) {
        // B tiles: prepped swizzled 32KB blocks -> straight copy
        {
            int blk;
            if (mode_a == 1) blk = (plane == 0) ? 0 : (plane < 4 ? 1 : 2);
            else blk = ntb * kchunks + kc;
            const float4* sH = (const float4*)(Bhi + (size_t)blk * 16384);
            const float4* sL = (const float4*)(Blo + (size_t)blk * 16384);
            float4* dH = (float4*)(smg + SM_BHI);
            float4* dL = (float4*)(smg + SM_BLO);
            for (int i = tid; i < 2048; i += GT) { dH[i] = sH[i]; dL[i] = sL[i]; }
        }
        // A tile: 2048 units of 16B; thread -> (row, unit)
        for (int i = tid; i < 2048; i += GT) {
            int r = i >> 4, u = i & 15;
            int e = m0 + r;
            int k0 = u * 8;
            float v[8];
            #pragma unroll
            for (int q = 0; q < 8; q++) v[q] = 0.0f;
            if (e < E) {
                if (mode_a == 0) {
                    const float* p = A + (size_t)e * lda + kc * 128 + k0;
                    float4 v0 = *(const float4*)(p);
                    float4 v1 = *(const float4*)(p + 4);
                    v[0]=v0.x; v[1]=v0.y; v[2]=v0.z; v[3]=v0.w;
                    v[4]=v1.x; v[5]=v1.y; v[6]=v1.z; v[7]=v1.w;
                } else if (plane == 0) {
                    const float* p = gate + (size_t)e * NM + k0;
                    float4 v0 = *(const float4*)(p);
                    float4 v1 = *(const float4*)(p + 4);
                    v[0]=v0.x; v[1]=v0.y; v[2]=v0.z; v[3]=v0.w;
                    v[4]=v1.x; v[5]=v1.y; v[6]=v1.z; v[7]=v1.w;
                } else {
                    const float* p = A + (size_t)e * lda + plane * 128 + k0;
                    int go = (plane < 4) ? 128 : 256;
                    const float* gp = gate + (size_t)e * NM + go + k0;
                    float4 n0v = *(const float4*)(p);
                    float4 n1v = *(const float4*)(p + 4);
                    float4 g0v = *(const float4*)(gp);
                    float4 g1v = *(const float4*)(gp + 4);
                    v[0]=n0v.x*g0v.x; v[1]=n0v.y*g0v.y; v[2]=n0v.z*g0v.z; v[3]=n0v.w*g0v.w;
                    v[4]=n1v.x*g1v.x; v[5]=n1v.y*g1v.y; v[6]=n1v.z*g1v.z; v[7]=n1v.w*g1v.w;
                }
            }
            uint32_t hi[4], lo[4];
            #pragma unroll
            for (int q = 0; q < 4; q++) {
                __nv_bfloat16 h0 = __float2bfloat16(v[2*q]);
                __nv_bfloat16 h1 = __float2bfloat16(v[2*q+1]);
                __nv_bfloat16 l0 = __float2bfloat16(v[2*q]   - __bfloat162float(h0));
                __nv_bfloat16 l1 = __float2bfloat16(v[2*q+1] - __bfloat162float(h1));
                __nv_bfloat162 h2(h0, h1), l2(l0, l1);
                hi[q] = *(uint32_t*)&h2;
                lo[q] = *(uint32_t*)&l2;
            }
            int off = sw_unit(r, u) * 16;
            *(uint4*)(smg + SM_AHI + off) = make_uint4(hi[0], hi[1], hi[2], hi[3]);
            *(uint4*)(smg + SM_ALO + off) = make_uint4(lo[0], lo[1], lo[2], lo[3]);
        }
        __syncthreads();

        #pragma unroll
        for (int pass = 0; pass < 3; pass++) {
            uint32_t Abase = smb + ((pass == 2) ? SM_ALO : SM_AHI);
            uint32_t Bbase = smb + ((pass == 1) ? SM_BLO : SM_BHI);
            #pragma unroll
            for (int ks = 0; ks < 8; ks++) {
                uint32_t a[2][4];
                #pragma unroll
                for (int mt = 0; mt < 2; mt++) {
                    int row = wm0 + mt * 16 + (lane & 15);
                    int u = ks * 2 + (lane >> 4);
                    ldmat_x4(a[mt], Abase + sw_unit(row, u) * 16);
                }
                uint32_t b[4][4];
                #pragma unroll
                for (int nq = 0; nq < 4; nq++) {
                    int n = wn0 + nq * 16 + (lane >> 4) * 8 + (lane & 7);
                    int u = ks * 2 + ((lane >> 3) & 1);
                    ldmat_x4(b[nq], Bbase + sw_unit(n, u) * 16);
                }
                #pragma unroll
                for (int mt = 0; mt < 2; mt++)
                    #pragma unroll
                    for (int nt = 0; nt < 8; nt++)
                        mma_bf16(acc[mt][nt], a[mt], b[nt >> 1][(nt & 1) * 2],
                                 b[nt >> 1][(nt & 1) * 2 + 1]);
            }
        }
        __syncthreads();
    }

    // ---------------- epilogue ----------------
    const int qr = lane >> 2;
    const int qc = (lane & 3) * 2;
    #pragma unroll
    for (int mt = 0; mt < 2; mt++) {
        #pragma unroll
        for (int nt = 0; nt < 8; nt++) {
            int cl = wn0 + nt * 8 + qc;         // local col 0..127
            float* c = acc[mt][nt];
            #pragma unroll
            for (int rr = 0; rr < 2; rr++) {
                int e = m0 + wm0 + mt * 16 + qr + rr * 8;
                if (e >= E) continue;
                float v0 = c[rr * 2], v1 = c[rr * 2 + 1];
                if (mode_ep == 3) {
                    v0 *= S128; v1 *= S128;
                    int j0, j1;
                    if (plane == 0) {
                        j0 = cl; j1 = cl + 1;
                        v0 += bias[cl]; v1 += bias[cl + 1];
                    } else if (plane < 4) {
                        j0 = 128 + cl * 3 + (plane - 1);
                        j1 = j0 + 3;
                    } else {
                        j0 = 512 + cl * 5 + (plane - 4);
                        j1 = j0 + 5;
                    }
                    OUT[(size_t)e * TOT + j0] = v0 + npa[(size_t)e * TOT + j0];
                    OUT[(size_t)e * TOT + j1] = v1 + npa[(size_t)e * TOT + j1];
                } else {
                    int n = ntb * 128 + cl;
                    if (bias) { v0 += bias[n]; v1 += bias[n + 1]; }
                    if (mode_ep == 1) { v0 = silu_f(v0); v1 = silu_f(v1); }
                    else if (mode_ep == 2) {
                        v0 *= mul[(size_t)e * MUL + cl];
                        v1 *= mul[(size_t)e * MUL + cl + 1];
                    }
                    OUT[(size_t)e * ldo + n]     = v0;
                    OUT[(size_t)e * ldo + n + 1] = v1;
                }
            }
        }
    }
}

// ---------------- launch ----------------
extern "C" void kernel_launch(void* const* d_in, const int* in_sizes, int n_in,
                              void* d_out, int out_size) {
    const float* node_attr = (const float*)d_in[0];
    const float* edge_attr = (const float*)d_in[1];
    const int*   dst       = (const int*)d_in[2];
    const int*   src       = (const int*)d_in[3];
    const float* npa       = (const float*)d_in[4];
    const float* W_inner   = (const float*)d_in[5];
    const float* b_inner   = (const float*)d_in[6];
    const float* W_n       = (const float*)d_in[7];
    const float* b_n       = (const float*)d_in[8];
    const float* W_out     = (const float*)d_in[9];
    const float* b_out     = (const float*)d_in[10];
    const float* pW1       = (const float*)d_in[11];
    const float* pb1       = (const float*)d_in[12];
    const float* pW2       = (const float*)d_in[13];
    const float* pb2       = (const float*)d_in[14];
    const float* gW1       = (const float*)d_in[15];
    const float* gb1       = (const float*)d_in[16];
    const float* gW2       = (const float*)d_in[17];
    const float* gb2       = (const float*)d_in[18];
    const float* fcEW1     = (const float*)d_in[19];
    const float* fcEW2     = (const float*)d_in[20];
    const float* fcW1      = (const float*)d_in[21];
    const float* fcb1      = (const float*)d_in[22];
    const float* fcW2      = (const float*)d_in[23];
    const float* fcb2      = (const float*)d_in[24];

    int N = in_sizes[0] / TOT;
    int E = in_sizes[2];
    int mt = (E + 127) / 128;

    void *p_s0f, *p_h, *p_w, *p_np, *p_g, *p_we, *p_pwhi, *p_pwlo;
    cudaGetSymbolAddress(&p_s0f, g_s0f);
    cudaGetSymbolAddress(&p_h,   g_h);
    cudaGetSymbolAddress(&p_w,   g_w);
    cudaGetSymbolAddress(&p_np,  g_np);
    cudaGetSymbolAddress(&p_g,   g_g);
    cudaGetSymbolAddress(&p_we,  g_we);
    cudaGetSymbolAddress(&p_pwhi, g_pw_hi);
    cudaGetSymbolAddress(&p_pwlo, g_pw_lo);
    const __nv_bfloat16* pwhi = (const __nv_bfloat16*)p_pwhi;
    const __nv_bfloat16* pwlo = (const __nv_bfloat16*)p_pwlo;

    size_t smem_node = (size_t)(TN * XP + 2 * TN * AP) * sizeof(float);
    cudaFuncSetAttribute(node_kernel, cudaFuncAttributeMaxDynamicSharedMemorySize, (int)smem_node);
    cudaFuncSetAttribute(gemm_kernel, cudaFuncAttributeMaxDynamicSharedMemorySize, SM_TOTAL);

    // weight prep
    prep_weight<<<(NM * MUL + 255) / 256, 256>>>(fcW1, NM, MUL, OFF_FCW1);
    prep_weight<<<(MUL * MUL + 255) / 256, 256>>>(fcW2, MUL, MUL, OFF_FCW2);
    prep_weight<<<(NM * NM + 255) / 256, 256>>>(gW1, NM, NM, OFF_NGW1);
    prep_weight<<<(NM * NM + 255) / 256, 256>>>(gW2, NM, NM, OFF_NGW2);
    for (int i = 0; i < 3; i++)
        prep_weight<<<(MUL * MUL + 255) / 256, 256>>>(W_out + i * MUL * MUL, MUL, MUL,
                                                      OFF_WOUT + i * 16384);

    // node stage
    node_kernel<<<(N + TN - 1) / TN, NTHREADS, smem_node>>>(
        node_attr, W_inner, b_inner, W_n, b_n, pW1, pb1, pW2, pb2, N);

    // edge scalar path
    k_mt<<<(E * 8 + 255) / 256, 256>>>(edge_attr, fcEW1, E);
    k_we<<<(E * MUL + 255) / 256, 256>>>(fcEW2, E);
    k_s0<<<(E * NM + 255) / 256, 256>>>(dst, src, E);

    // G1: h1 = silu(s0 @ fcW1 + fcb1)          [E x 128]
    gemm_kernel<<<dim3(mt, 1), GT, SM_TOTAL>>>(
        (const float*)p_s0f, NM, 3, pwhi + OFF_FCW1, pwlo + OFF_FCW1,
        (float*)p_h, MUL, fcb1, nullptr, nullptr, nullptr, 0, 1, E);

    // G2: w = (h1 @ fcW2 + fcb2) * we          [E x 128]
    gemm_kernel<<<dim3(mt, 1), GT, SM_TOTAL>>>(
        (const float*)p_h, MUL, 1, pwhi + OFF_FCW2, pwlo + OFF_FCW2,
        (float*)p_w, MUL, fcb2, (const float*)p_we, nullptr, nullptr, 0, 2, E);

    // np (planar) + f0'
    k_npf<<<(E * MUL + 255) / 256, 256>>>(dst, src, E);

    // G3: h = silu(f @ ngW1 + ngb1)            [E x 384]
    gemm_kernel<<<dim3(mt, 3), GT, SM_TOTAL>>>(
        (const float*)p_s0f, NM, 3, pwhi + OFF_NGW1, pwlo + OFF_NGW1,
        (float*)p_h, NM, gb1, nullptr, nullptr, nullptr, 0, 1, E);

    // G4: g = h @ ngW2 + ngb2                  [E x 384]
    gemm_kernel<<<dim3(mt, 3), GT, SM_TOTAL>>>(
        (const float*)p_h, NM, 3, pwhi + OFF_NGW2, pwlo + OFF_NGW2,
        (float*)p_g, NM, gb2, nullptr, nullptr, nullptr, 0, 0, E);

    // G5: out = irrep_linear(gate(np, g), W_out)*S128 + b_out + npa  (9 planes, scatter)
    gemm_kernel<<<dim3(mt, 9), GT, SM_TOTAL>>>(
        (const float*)p_np, TOT, 1, pwhi + OFF_WOUT, pwlo + OFF_WOUT,
        (float*)d_out, TOT, b_out, nullptr, (const float*)p_g, npa, 1, 3, E);
}

// round 5
// speedup vs baseline: 3.9553x; 1.3499x over previous
#include <cuda_runtime.h>
#include <cuda_bf16.h>
#include <cstdint>
#include <cstddef>

#define MUL 128
#define TOT 1152
#define NM  384
#define MAXN 4096
#define MAXE 65536
#define S128 0.08838834764831845f

// ---------------- scratch ----------------
__device__ float g_na0[MAXN * TOT];
__device__ float g_na [MAXN * TOT];
__device__ float g_xp [MAXN * TOT];          // planar node_attr, later gated
__device__ float g_nf [MAXN * NM];           // node f0
__device__ float g_nh [MAXN * NM];           // node hidden
__device__ float g_ng [MAXN * NM];           // node gates
__device__ float g_s0f[(size_t)MAXE * NM];   // s0, later reused as f0'
__device__ float g_mt [(size_t)MAXE * 8];
__device__ float g_we [(size_t)MAXE * MUL];
__device__ float g_h  [(size_t)MAXE * NM];   // h1 (ld 128), later h (ld 384)
__device__ float g_w  [(size_t)MAXE * MUL];
__device__ float g_np [(size_t)MAXE * TOT];
__device__ float g_g  [(size_t)MAXE * NM];

// prepped weights (bf16 hi/lo, transposed [n][k], 128x64 blocks, xor-swizzled)
#define BLK 8192
#define OFF_FCW1 0
#define OFF_FCW2 49152
#define OFF_NGW1 65536
#define OFF_NGW2 212992
#define OFF_WOUT 360448
#define OFF_WIN  409600
#define OFF_WN   458752
#define OFF_PW1  507904
#define OFF_PW2  655360
#define PW_TOTAL 802816
__device__ __nv_bfloat16 g_pw_hi[PW_TOTAL];
__device__ __nv_bfloat16 g_pw_lo[PW_TOTAL];

__device__ __forceinline__ uint32_t smem_to_u32(const void* p) {
    uint32_t a;
    asm("{ .reg .u64 t; cvta.to.shared.u64 t, %1; cvt.u32.u64 %0, t; }" : "=r"(a) : "l"(p));
    return a;
}
__device__ __forceinline__ float silu_f(float x) { return x / (1.0f + __expf(-x)); }
__device__ __forceinline__ float ssp_f(float x) {
    return fmaxf(x, 0.0f) + log1pf(__expf(-fabsf(x))) - 0.69314718055994531f;
}

// 16B-unit index inside a 128x64 bf16 tile (128B rows, xor swizzle)
__device__ __forceinline__ int sw_unit(int row, int u) {
    return row * 8 + (u ^ (row & 7));
}

__device__ __forceinline__ void ldmat_x4(uint32_t* r, uint32_t addr) {
    asm volatile("ldmatrix.sync.aligned.m8n8.x4.shared.b16 {%0,%1,%2,%3}, [%4];"
        : "=r"(r[0]), "=r"(r[1]), "=r"(r[2]), "=r"(r[3]) : "r"(addr));
}
__device__ __forceinline__ void mma_bf16(float* c, const uint32_t* a, uint32_t b0, uint32_t b1) {
    asm volatile("mma.sync.aligned.m16n8k16.row.col.f32.bf16.bf16.f32 "
        "{%0,%1,%2,%3}, {%4,%5,%6,%7}, {%8,%9}, {%0,%1,%2,%3};"
        : "+f"(c[0]), "+f"(c[1]), "+f"(c[2]), "+f"(c[3])
        : "r"(a[0]), "r"(a[1]), "r"(a[2]), "r"(a[3]), "r"(b0), "r"(b1));
}
__device__ __forceinline__ void cp_async16(uint32_t dst, const void* src) {
    asm volatile("cp.async.ca.shared.global [%0], [%1], 16;" :: "r"(dst), "l"(src));
}
#define CP_COMMIT() asm volatile("cp.async.commit_group;" ::: "memory")
#define CP_WAIT0()  asm volatile("cp.async.wait_group 0;" ::: "memory")

// ---------------- weight prep ----------------
// src fp32 [K x N] row-major -> blocks [nt][kc64] of B[n][k] (128x64) swizzled
__global__ void prep_weight(const float* __restrict__ W, int K, int N, int dstoff) {
    int idx = blockIdx.x * blockDim.x + threadIdx.x;
    if (idx >= K * N) return;
    int kg = idx / N, ng = idx - kg * N;
    float x = W[idx];
    __nv_bfloat16 h = __float2bfloat16(x);
    __nv_bfloat16 l = __float2bfloat16(x - __bfloat162float(h));
    int kch = K >> 6;
    int nt = ng >> 7, n = ng & 127, kc = kg >> 6, k = kg & 63;
    int blk = nt * kch + kc;
    int e = blk * BLK + sw_unit(n, k >> 3) * 8 + (k & 7) + dstoff;
    g_pw_hi[e] = h;
    g_pw_lo[e] = l;
}

// ---------------- elementwise kernels ----------------
// planarize node_attr -> g_xp, and f0 -> g_nf
__global__ void k_xplan(const float* __restrict__ na, int N) {
    int idx = blockIdx.x * blockDim.x + threadIdx.x;
    if (idx >= N * MUL) return;
    int n = idx >> 7, u = idx & 127;
    const float* x = na + (size_t)n * TOT;
    float v[9];
    v[0] = x[u];
    #pragma unroll
    for (int c = 0; c < 3; c++) v[1 + c] = x[128 + u * 3 + c];
    #pragma unroll
    for (int c = 0; c < 5; c++) v[4 + c] = x[512 + u * 5 + c];
    float* xp = g_xp + (size_t)n * TOT;
    #pragma unroll
    for (int p = 0; p < 9; p++) xp[p * 128 + u] = v[p];
    float* f = g_nf + (size_t)n * NM;
    f[u] = v[0];
    f[128 + u] = sqrtf(v[1] * v[1] + v[2] * v[2] + v[3] * v[3]);
    f[256 + u] = sqrtf(v[4] * v[4] + v[5] * v[5] + v[6] * v[6] + v[7] * v[7] + v[8] * v[8]);
}

// gate g_xp in place with g_ng
__global__ void k_gate_node(int N) {
    int idx = blockIdx.x * blockDim.x + threadIdx.x;
    if (idx >= N * MUL) return;
    int n = idx >> 7, u = idx & 127;
    const float* g = g_ng + (size_t)n * NM;
    float* xp = g_xp + (size_t)n * TOT;
    float g1 = g[128 + u], g2 = g[256 + u];
    xp[u] = g[u];
    #pragma unroll
    for (int p = 1; p < 4; p++) xp[p * 128 + u] *= g1;
    #pragma unroll
    for (int p = 4; p < 9; p++) xp[p * 128 + u] *= g2;
}

__global__ void k_mt(const float* __restrict__ ea, const float* __restrict__ W1, int E) {
    int idx = blockIdx.x * blockDim.x + threadIdx.x;
    if (idx >= E * 8) return;
    int e = idx >> 3, j = idx & 7;
    const float* a = ea + (size_t)e * 64;
    float acc = 0.0f;
    #pragma unroll 16
    for (int i = 0; i < 64; i++) acc += a[i] * W1[i * 8 + j];
    g_mt[idx] = ssp_f(acc * 0.125f);
}

__global__ void k_we(const float* __restrict__ W2, int E) {
    int idx = blockIdx.x * blockDim.x + threadIdx.x;
    if (idx >= E * MUL) return;
    int e = idx >> 7, n = idx & 127;
    const float* m = g_mt + (size_t)e * 8;
    float acc = 0.0f;
    #pragma unroll
    for (int j = 0; j < 8; j++) acc += m[j] * W2[j * MUL + n];
    g_we[idx] = acc * 0.35355339059327373f;
}

__global__ void k_s0(const int* __restrict__ dst, const int* __restrict__ src, int E) {
    int idx = blockIdx.x * blockDim.x + threadIdx.x;
    if (idx >= E * NM) return;
    int e = idx / NM, k = idx - e * NM;
    const float* nd = g_na0 + (size_t)dst[e] * TOT;
    const float* ns = g_na0 + (size_t)src[e] * TOT;
    float val;
    if (k < 128) val = 0.5f * (nd[k] + ns[k]);
    else if (k < 256) {
        int u = k - 128;
        val = (nd[128 + u] * ns[128 + u] + nd[256 + u] * ns[256 + u]
             + nd[384 + u] * ns[384 + u]) * 0.57735026918962576f;
    } else {
        int u = k - 256;
        val = (nd[512 + u] * ns[512 + u] + nd[640 + u] * ns[640 + u]
             + nd[768 + u] * ns[768 + u] + nd[896 + u] * ns[896 + u]
             + nd[1024 + u] * ns[1024 + u]) * 0.44721359549995794f;
    }
    g_s0f[idx] = val;
}

__global__ void k_npf(const int* __restrict__ dst, const int* __restrict__ src, int E) {
    int idx = blockIdx.x * blockDim.x + threadIdx.x;
    if (idx >= E * MUL) return;
    int e = idx >> 7, u = idx & 127;
    const float* ns = g_na + (size_t)src[e] * TOT;
    const float* nd = g_na + (size_t)dst[e] * TOT;
    const float* w = g_w + (size_t)e * MUL;
    float np[9];
    np[0] = (ns[u] + nd[u]) * w[u / 9];
    #pragma unroll
    for (int p = 1; p < 4; p++) {
        int j = 128 + u * 3 + (p - 1);
        np[p] = (ns[p * 128 + u] + nd[p * 128 + u]) * w[j / 9];
    }
    #pragma unroll
    for (int p = 4; p < 9; p++) {
        int j = 512 + u * 5 + (p - 4);
        np[p] = (ns[p * 128 + u] + nd[p * 128 + u]) * w[j / 9];
    }
    float* npo = g_np + (size_t)e * TOT;
    #pragma unroll
    for (int p = 0; p < 9; p++) npo[p * 128 + u] = np[p];
    float* f = g_s0f + (size_t)e * NM;
    f[u] = np[0];
    f[128 + u] = sqrtf(np[1] * np[1] + np[2] * np[2] + np[3] * np[3]);
    f[256 + u] = sqrtf(np[4] * np[4] + np[5] * np[5] + np[6] * np[6]
                     + np[7] * np[7] + np[8] * np[8]);
}

// ---------------- mma.sync GEMM ----------------
// CTA: 128 rows x 128 cols, K in chunks of 64. 8 warps (4x2), warp tile 32x64.
// split-bf16: D = AhiBhi + AhiBlo + AloBhi (fp32 reg accum). 64KB smem, 2 CTAs/SM.
#define GT 256
#define SM_AHI 0
#define SM_ALO 16384
#define SM_BHI 32768
#define SM_BLO 49152
#define SM_TOTAL 65536

// mode_a: 0 plain A[r*lda + kc*64+k], colblock=by
//         1 gated planar (plane=by): plane0 A=gate, else A[plane*128+...]*gate
//         2 planar plain (plane=by): A[r*lda + plane*128 + kc*64+k]
// mode_ep: 0 +bias ; 1 silu(+bias) ; 2 (acc+bias)*mul ; 3 irrep scatter *S128+bias0+npa
//          4 planar *S128 (+bias if plane0), col = plane*128+cl
__global__ void __launch_bounds__(GT, 2) gemm_kernel(
    const float* __restrict__ A, int lda, int kchunks,
    const __nv_bfloat16* __restrict__ Bhi, const __nv_bfloat16* __restrict__ Blo,
    float* __restrict__ OUT, int ldo,
    const float* __restrict__ bias,
    const float* __restrict__ mul,
    const float* __restrict__ gate,
    const float* __restrict__ npa,
    int mode_a, int mode_ep, int E)
{
    extern __shared__ char smg[];
    uint32_t smb = smem_to_u32(smg);
    const int tid = threadIdx.x;
    const int wid = tid >> 5;
    const int lane = tid & 31;
    const int m0 = blockIdx.x * 128;
    const int by = blockIdx.y;
    const int plane = (mode_a != 0) ? by : 0;
    const int ntb = (mode_a != 0) ? 0 : by;

    const int wm0 = (wid & 3) * 32;
    const int wn0 = (wid >> 2) * 64;

    float acc[2][8][4];
    #pragma unroll
    for (int i = 0; i < 2; i++)
        #pragma unroll
        for (int j = 0; j < 8; j++)
            #pragma unroll
            for (int q = 0; q < 4; q++) acc[i][j][q] = 0.0f;

    int bsel = 0;
    if (mode_a != 0) bsel = (plane == 0) ? 0 : (plane < 4 ? 1 : 2);

    for (int kc = 0; kc < kchunks; kc++) {
        // B tile via cp.async (prepped 16KB blocks)
        {
            int blk = (mode_a != 0) ? (bsel * kchunks + kc) : (ntb * kchunks + kc);
            const char* sH = (const char*)(Bhi + (size_t)blk * BLK);
            const char* sL = (const char*)(Blo + (size_t)blk * BLK);
            for (int i = tid; i < 1024; i += GT) {
                cp_async16(smb + SM_BHI + i * 16, sH + i * 16);
                cp_async16(smb + SM_BLO + i * 16, sL + i * 16);
            }
            CP_COMMIT();
        }
        // A tile: 1024 16B-units; unit = 8 k-elems
        for (int i = tid; i < 1024; i += GT) {
            int r = i >> 3, u = i & 7;
            int e = m0 + r;
            int k0 = u * 8;
            float v[8];
            #pragma unroll
            for (int q = 0; q < 8; q++) v[q] = 0.0f;
            if (e < E) {
                if (mode_a == 0) {
                    const float* p = A + (size_t)e * lda + kc * 64 + k0;
                    float4 v0 = *(const float4*)(p);
                    float4 v1 = *(const float4*)(p + 4);
                    v[0]=v0.x; v[1]=v0.y; v[2]=v0.z; v[3]=v0.w;
                    v[4]=v1.x; v[5]=v1.y; v[6]=v1.z; v[7]=v1.w;
                } else if (mode_a == 2) {
                    const float* p = A + (size_t)e * lda + plane * 128 + kc * 64 + k0;
                    float4 v0 = *(const float4*)(p);
                    float4 v1 = *(const float4*)(p + 4);
                    v[0]=v0.x; v[1]=v0.y; v[2]=v0.z; v[3]=v0.w;
                    v[4]=v1.x; v[5]=v1.y; v[6]=v1.z; v[7]=v1.w;
                } else if (plane == 0) {
                    const float* p = gate + (size_t)e * NM + kc * 64 + k0;
                    float4 v0 = *(const float4*)(p);
                    float4 v1 = *(const float4*)(p + 4);
                    v[0]=v0.x; v[1]=v0.y; v[2]=v0.z; v[3]=v0.w;
                    v[4]=v1.x; v[5]=v1.y; v[6]=v1.z; v[7]=v1.w;
                } else {
                    const float* p = A + (size_t)e * lda + plane * 128 + kc * 64 + k0;
                    int go = (plane < 4) ? 128 : 256;
                    const float* gp = gate + (size_t)e * NM + go + kc * 64 + k0;
                    float4 n0v = *(const float4*)(p);
                    float4 n1v = *(const float4*)(p + 4);
                    float4 g0v = *(const float4*)(gp);
                    float4 g1v = *(const float4*)(gp + 4);
                    v[0]=n0v.x*g0v.x; v[1]=n0v.y*g0v.y; v[2]=n0v.z*g0v.z; v[3]=n0v.w*g0v.w;
                    v[4]=n1v.x*g1v.x; v[5]=n1v.y*g1v.y; v[6]=n1v.z*g1v.z; v[7]=n1v.w*g1v.w;
                }
            }
            uint32_t hi[4], lo[4];
            #pragma unroll
            for (int q = 0; q < 4; q++) {
                __nv_bfloat16 h0 = __float2bfloat16(v[2*q]);
                __nv_bfloat16 h1 = __float2bfloat16(v[2*q+1]);
                __nv_bfloat16 l0 = __float2bfloat16(v[2*q]   - __bfloat162float(h0));
                __nv_bfloat16 l1 = __float2bfloat16(v[2*q+1] - __bfloat162float(h1));
                __nv_bfloat162 h2(h0, h1), l2(l0, l1);
                hi[q] = *(uint32_t*)&h2;
                lo[q] = *(uint32_t*)&l2;
            }
            int off = sw_unit(r, u) * 16;
            *(uint4*)(smg + SM_AHI + off) = make_uint4(hi[0], hi[1], hi[2], hi[3]);
            *(uint4*)(smg + SM_ALO + off) = make_uint4(lo[0], lo[1], lo[2], lo[3]);
        }
        CP_WAIT0();
        __syncthreads();

        #pragma unroll
        for (int pass = 0; pass < 3; pass++) {
            uint32_t Abase = smb + ((pass == 2) ? SM_ALO : SM_AHI);
            uint32_t Bbase = smb + ((pass == 1) ? SM_BLO : SM_BHI);
            #pragma unroll
            for (int ks = 0; ks < 4; ks++) {
                uint32_t a[2][4];
                #pragma unroll
                for (int mt = 0; mt < 2; mt++) {
                    int row = wm0 + mt * 16 + (lane & 15);
                    int u = ks * 2 + (lane >> 4);
                    ldmat_x4(a[mt], Abase + sw_unit(row, u) * 16);
                }
                uint32_t b[4][4];
                #pragma unroll
                for (int nq = 0; nq < 4; nq++) {
                    int n = wn0 + nq * 16 + (lane >> 4) * 8 + (lane & 7);
                    int u = ks * 2 + ((lane >> 3) & 1);
                    ldmat_x4(b[nq], Bbase + sw_unit(n, u) * 16);
                }
                #pragma unroll
                for (int mt = 0; mt < 2; mt++)
                    #pragma unroll
                    for (int nt = 0; nt < 8; nt++)
                        mma_bf16(acc[mt][nt], a[mt], b[nt >> 1][(nt & 1) * 2],
                                 b[nt >> 1][(nt & 1) * 2 + 1]);
            }
        }
        __syncthreads();
    }

    // ---------------- epilogue ----------------
    const int qr = lane >> 2;
    const int qc = (lane & 3) * 2;
    #pragma unroll
    for (int mt = 0; mt < 2; mt++) {
        #pragma unroll
        for (int nt = 0; nt < 8; nt++) {
            int cl = wn0 + nt * 8 + qc;
            float* c = acc[mt][nt];
            #pragma unroll
            for (int rr = 0; rr < 2; rr++) {
                int e = m0 + wm0 + mt * 16 + qr + rr * 8;
                if (e >= E) continue;
                float v0 = c[rr * 2], v1 = c[rr * 2 + 1];
                if (mode_ep == 3) {
                    v0 *= S128; v1 *= S128;
                    int j0, j1;
                    if (plane == 0) {
                        j0 = cl; j1 = cl + 1;
                        v0 += bias[cl]; v1 += bias[cl + 1];
                    } else if (plane < 4) {
                        j0 = 128 + cl * 3 + (plane - 1);
                        j1 = j0 + 3;
                    } else {
                        j0 = 512 + cl * 5 + (plane - 4);
                        j1 = j0 + 5;
                    }
                    OUT[(size_t)e * TOT + j0] = v0 + npa[(size_t)e * TOT + j0];
                    OUT[(size_t)e * TOT + j1] = v1 + npa[(size_t)e * TOT + j1];
                } else if (mode_ep == 4) {
                    v0 *= S128; v1 *= S128;
                    if (plane == 0 && bias) { v0 += bias[cl]; v1 += bias[cl + 1]; }
                    int n = plane * 128 + cl;
                    OUT[(size_t)e * ldo + n]     = v0;
                    OUT[(size_t)e * ldo + n + 1] = v1;
                } else {
                    int n = ntb * 128 + cl;
                    if (bias) { v0 += bias[n]; v1 += bias[n + 1]; }
                    if (mode_ep == 1) { v0 = silu_f(v0); v1 = silu_f(v1); }
                    else if (mode_ep == 2) {
                        v0 *= mul[(size_t)e * MUL + cl];
                        v1 *= mul[(size_t)e * MUL + cl + 1];
                    }
                    OUT[(size_t)e * ldo + n]     = v0;
                    OUT[(size_t)e * ldo + n + 1] = v1;
                }
            }
        }
    }
}

// ---------------- launch ----------------
extern "C" void kernel_launch(void* const* d_in, const int* in_sizes, int n_in,
                              void* d_out, int out_size) {
    const float* node_attr = (const float*)d_in[0];
    const float* edge_attr = (const float*)d_in[1];
    const int*   dst       = (const int*)d_in[2];
    const int*   src       = (const int*)d_in[3];
    const float* npa       = (const float*)d_in[4];
    const float* W_inner   = (const float*)d_in[5];
    const float* b_inner   = (const float*)d_in[6];
    const float* W_n       = (const float*)d_in[7];
    const float* b_n       = (const float*)d_in[8];
    const float* W_out     = (const float*)d_in[9];
    const float* b_out     = (const float*)d_in[10];
    const float* pW1       = (const float*)d_in[11];
    const float* pb1       = (const float*)d_in[12];
    const float* pW2       = (const float*)d_in[13];
    const float* pb2       = (const float*)d_in[14];
    const float* gW1       = (const float*)d_in[15];
    const float* gb1       = (const float*)d_in[16];
    const float* gW2       = (const float*)d_in[17];
    const float* gb2       = (const float*)d_in[18];
    const float* fcEW1     = (const float*)d_in[19];
    const float* fcEW2     = (const float*)d_in[20];
    const float* fcW1      = (const float*)d_in[21];
    const float* fcb1      = (const float*)d_in[22];
    const float* fcW2      = (const float*)d_in[23];
    const float* fcb2      = (const float*)d_in[24];

    int N = in_sizes[0] / TOT;
    int E = in_sizes[2];
    int mt = (E + 127) / 128;
    int nt = (N + 127) / 128;

    void *p_s0f, *p_h, *p_w, *p_np, *p_g, *p_we, *p_pwhi, *p_pwlo;
    void *p_xp, *p_nf, *p_nh, *p_ng, *p_na0, *p_na;
    cudaGetSymbolAddress(&p_s0f, g_s0f);
    cudaGetSymbolAddress(&p_h,   g_h);
    cudaGetSymbolAddress(&p_w,   g_w);
    cudaGetSymbolAddress(&p_np,  g_np);
    cudaGetSymbolAddress(&p_g,   g_g);
    cudaGetSymbolAddress(&p_we,  g_we);
    cudaGetSymbolAddress(&p_pwhi, g_pw_hi);
    cudaGetSymbolAddress(&p_pwlo, g_pw_lo);
    cudaGetSymbolAddress(&p_xp,  g_xp);
    cudaGetSymbolAddress(&p_nf,  g_nf);
    cudaGetSymbolAddress(&p_nh,  g_nh);
    cudaGetSymbolAddress(&p_ng,  g_ng);
    cudaGetSymbolAddress(&p_na0, g_na0);
    cudaGetSymbolAddress(&p_na,  g_na);
    const __nv_bfloat16* pwhi = (const __nv_bfloat16*)p_pwhi;
    const __nv_bfloat16* pwlo = (const __nv_bfloat16*)p_pwlo;

    cudaFuncSetAttribute(gemm_kernel, cudaFuncAttributeMaxDynamicSharedMemorySize, SM_TOTAL);

    // ---- weight prep ----
    prep_weight<<<(NM * MUL + 255) / 256, 256>>>(fcW1, NM, MUL, OFF_FCW1);
    prep_weight<<<(MUL * MUL + 255) / 256, 256>>>(fcW2, MUL, MUL, OFF_FCW2);
    prep_weight<<<(NM * NM + 255) / 256, 256>>>(gW1, NM, NM, OFF_NGW1);
    prep_weight<<<(NM * NM + 255) / 256, 256>>>(gW2, NM, NM, OFF_NGW2);
    prep_weight<<<(NM * NM + 255) / 256, 256>>>(pW1, NM, NM, OFF_PW1);
    prep_weight<<<(NM * NM + 255) / 256, 256>>>(pW2, NM, NM, OFF_PW2);
    for (int i = 0; i < 3; i++) {
        prep_weight<<<(MUL * MUL + 255) / 256, 256>>>(W_out + i * MUL * MUL, MUL, MUL,
                                                      OFF_WOUT + i * 2 * BLK);
        prep_weight<<<(MUL * MUL + 255) / 256, 256>>>(W_inner + i * MUL * MUL, MUL, MUL,
                                                      OFF_WIN + i * 2 * BLK);
        prep_weight<<<(MUL * MUL + 255) / 256, 256>>>(W_n + i * MUL * MUL, MUL, MUL,
                                                      OFF_WN + i * 2 * BLK);
    }

    // ---- node stage ----
    k_xplan<<<(N * MUL + 255) / 256, 256>>>(node_attr, N);

    // na0 = irrep(xp, W_inner)  [N x TOT planar]
    gemm_kernel<<<dim3(nt, 9), GT, SM_TOTAL>>>(
        (const float*)p_xp, TOT, 2, pwhi + OFF_WIN, pwlo + OFF_WIN,
        (float*)p_na0, TOT, b_inner, nullptr, nullptr, nullptr, 2, 4, N);

    // nh = silu(nf @ pW1 + pb1)
    gemm_kernel<<<dim3(nt, 3), GT, SM_TOTAL>>>(
        (const float*)p_nf, NM, 6, pwhi + OFF_PW1, pwlo + OFF_PW1,
        (float*)p_nh, NM, pb1, nullptr, nullptr, nullptr, 0, 1, N);

    // ng = nh @ pW2 + pb2
    gemm_kernel<<<dim3(nt, 3), GT, SM_TOTAL>>>(
        (const float*)p_nh, NM, 6, pwhi + OFF_PW2, pwlo + OFF_PW2,
        (float*)p_ng, NM, pb2, nullptr, nullptr, nullptr, 0, 0, N);

    k_gate_node<<<(N * MUL + 255) / 256, 256>>>(N);

    // na = irrep(gated xp, W_n)
    gemm_kernel<<<dim3(nt, 9), GT, SM_TOTAL>>>(
        (const float*)p_xp, TOT, 2, pwhi + OFF_WN, pwlo + OFF_WN,
        (float*)p_na, TOT, b_n, nullptr, nullptr, nullptr, 2, 4, N);

    // ---- edge stage ----
    k_mt<<<(E * 8 + 255) / 256, 256>>>(edge_attr, fcEW1, E);
    k_we<<<(E * MUL + 255) / 256, 256>>>(fcEW2, E);
    k_s0<<<(E * NM + 255) / 256, 256>>>(dst, src, E);

    // G1: h1 = silu(s0 @ fcW1 + fcb1)          [E x 128]
    gemm_kernel<<<dim3(mt, 1), GT, SM_TOTAL>>>(
        (const float*)p_s0f, NM, 6, pwhi + OFF_FCW1, pwlo + OFF_FCW1,
        (float*)p_h, MUL, fcb1, nullptr, nullptr, nullptr, 0, 1, E);

    // G2: w = (h1 @ fcW2 + fcb2) * we          [E x 128]
    gemm_kernel<<<dim3(mt, 1), GT, SM_TOTAL>>>(
        (const float*)p_h, MUL, 2, pwhi + OFF_FCW2, pwlo + OFF_FCW2,
        (float*)p_w, MUL, fcb2, (const float*)p_we, nullptr, nullptr, 0, 2, E);

    // np (planar) + f0'
    k_npf<<<(E * MUL + 255) / 256, 256>>>(dst, src, E);

    // G3: h = silu(f @ ngW1 + ngb1)            [E x 384]
    gemm_kernel<<<dim3(mt, 3), GT, SM_TOTAL>>>(
        (const float*)p_s0f, NM, 6, pwhi + OFF_NGW1, pwlo + OFF_NGW1,
        (float*)p_h, NM, gb1, nullptr, nullptr, nullptr, 0, 1, E);

    // G4: g = h @ ngW2 + ngb2                  [E x 384]
    gemm_kernel<<<dim3(mt, 3), GT, SM_TOTAL>>>(
        (const float*)p_h, NM, 6, pwhi + OFF_NGW2, pwlo + OFF_NGW2,
        (float*)p_g, NM, gb2, nullptr, nullptr, nullptr, 0, 0, E);

    // G5: out = irrep(gate(np, g), W_out)*S128 + b_out + npa  (9 planes, scatter)
    gemm_kernel<<<dim3(mt, 9), GT, SM_TOTAL>>>(
        (const float*)p_np, TOT, 2, pwhi + OFF_WOUT, pwlo + OFF_WOUT,
        (float*)d_out, TOT, b_out, nullptr, (const float*)p_g, npa, 1, 3, E);
}

// round 6
// speedup vs baseline: 4.6169x; 1.1673x over previous
#include <cuda_runtime.h>
#include <cuda_bf16.h>
#include <cstdint>
#include <cstddef>

#define MUL 128
#define TOT 1152
#define NM  384
#define MAXN 4096
#define MAXE 65536
#define S128 0.08838834764831845f
#define IS3  0.57735026918962576f
#define IS5  0.44721359549995794f

// ---------------- scratch ----------------
__device__ float g_na0[MAXN * TOT];
__device__ float g_na [MAXN * TOT];
__device__ float g_xp [MAXN * TOT];          // planar node_attr, later gated
__device__ float g_nf [MAXN * NM];           // node f0
__device__ float g_nh [MAXN * NM];           // node hidden
__device__ float g_ng [MAXN * NM];           // node gates
__device__ float g_s0f[(size_t)MAXE * NM];   // f0'
__device__ float g_mt [(size_t)MAXE * 8];
__device__ float g_we [(size_t)MAXE * MUL];
__device__ float g_h  [(size_t)MAXE * NM];
__device__ float g_w  [(size_t)MAXE * MUL];
__device__ float g_np [(size_t)MAXE * TOT];  // G5 planar output
__device__ float g_g  [(size_t)MAXE * NM];

// prepped weights (bf16 hi/lo, transposed [n][k], 128x64 blocks, xor-swizzled)
#define BLK 8192
#define OFF_FCW1 0
#define OFF_FCW2 49152
#define OFF_NGW1 65536
#define OFF_NGW2 212992
#define OFF_WOUT 360448
#define OFF_WIN  409600
#define OFF_WN   458752
#define OFF_PW1  507904
#define OFF_PW2  655360
#define PW_TOTAL 802816
__device__ __nv_bfloat16 g_pw_hi[PW_TOTAL];
__device__ __nv_bfloat16 g_pw_lo[PW_TOTAL];

__device__ __forceinline__ uint32_t smem_to_u32(const void* p) {
    uint32_t a;
    asm("{ .reg .u64 t; cvta.to.shared.u64 t, %1; cvt.u32.u64 %0, t; }" : "=r"(a) : "l"(p));
    return a;
}
__device__ __forceinline__ float silu_f(float x) { return x / (1.0f + __expf(-x)); }
__device__ __forceinline__ float ssp_f(float x) {
    return fmaxf(x, 0.0f) + log1pf(__expf(-fabsf(x))) - 0.69314718055994531f;
}
__device__ __forceinline__ int sw_unit(int row, int u) {
    return row * 8 + (u ^ (row & 7));
}
__device__ __forceinline__ int merged_to_planar(int j) {
    if (j < 128) return j;
    if (j < 512) { int r = j - 128; int u = r / 3; int c = r - 3 * u; return (1 + c) * 128 + u; }
    int r = j - 512; int u = r / 5; int c = r - 5 * u; return (4 + c) * 128 + u;
}

__device__ __forceinline__ void ldmat_x4(uint32_t* r, uint32_t addr) {
    asm volatile("ldmatrix.sync.aligned.m8n8.x4.shared.b16 {%0,%1,%2,%3}, [%4];"
        : "=r"(r[0]), "=r"(r[1]), "=r"(r[2]), "=r"(r[3]) : "r"(addr));
}
__device__ __forceinline__ void mma_bf16(float* c, const uint32_t* a, uint32_t b0, uint32_t b1) {
    asm volatile("mma.sync.aligned.m16n8k16.row.col.f32.bf16.bf16.f32 "
        "{%0,%1,%2,%3}, {%4,%5,%6,%7}, {%8,%9}, {%0,%1,%2,%3};"
        : "+f"(c[0]), "+f"(c[1]), "+f"(c[2]), "+f"(c[3])
        : "r"(a[0]), "r"(a[1]), "r"(a[2]), "r"(a[3]), "r"(b0), "r"(b1));
}
__device__ __forceinline__ void cp_async16(uint32_t dst, const void* src) {
    asm volatile("cp.async.ca.shared.global [%0], [%1], 16;" :: "r"(dst), "l"(src));
}
#define CP_COMMIT() asm volatile("cp.async.commit_group;" ::: "memory")
#define CP_WAIT0()  asm volatile("cp.async.wait_group 0;" ::: "memory")

// ---------------- weight prep ----------------
__global__ void prep_weight(const float* __restrict__ W, int K, int N, int dstoff) {
    int idx = blockIdx.x * blockDim.x + threadIdx.x;
    if (idx >= K * N) return;
    int kg = idx / N, ng = idx - kg * N;
    float x = W[idx];
    __nv_bfloat16 h = __float2bfloat16(x);
    __nv_bfloat16 l = __float2bfloat16(x - __bfloat162float(h));
    int kch = K >> 6;
    int nt = ng >> 7, n = ng & 127, kc = kg >> 6, k = kg & 63;
    int blk = nt * kch + kc;
    int e = blk * BLK + sw_unit(n, k >> 3) * 8 + (k & 7) + dstoff;
    g_pw_hi[e] = h;
    g_pw_lo[e] = l;
}

// ---------------- elementwise kernels ----------------
__global__ void k_xplan(const float* __restrict__ na, int N) {
    int idx = blockIdx.x * blockDim.x + threadIdx.x;
    if (idx >= N * MUL) return;
    int n = idx >> 7, u = idx & 127;
    const float* x = na + (size_t)n * TOT;
    float v[9];
    v[0] = x[u];
    #pragma unroll
    for (int c = 0; c < 3; c++) v[1 + c] = x[128 + u * 3 + c];
    #pragma unroll
    for (int c = 0; c < 5; c++) v[4 + c] = x[512 + u * 5 + c];
    float* xp = g_xp + (size_t)n * TOT;
    #pragma unroll
    for (int p = 0; p < 9; p++) xp[p * 128 + u] = v[p];
    float* f = g_nf + (size_t)n * NM;
    f[u] = v[0];
    f[128 + u] = sqrtf(v[1] * v[1] + v[2] * v[2] + v[3] * v[3]);
    f[256 + u] = sqrtf(v[4] * v[4] + v[5] * v[5] + v[6] * v[6] + v[7] * v[7] + v[8] * v[8]);
}

__global__ void k_gate_node(int N) {
    int idx = blockIdx.x * blockDim.x + threadIdx.x;
    if (idx >= N * MUL) return;
    int n = idx >> 7, u = idx & 127;
    const float* g = g_ng + (size_t)n * NM;
    float* xp = g_xp + (size_t)n * TOT;
    float g1 = g[128 + u], g2 = g[256 + u];
    xp[u] = g[u];
    #pragma unroll
    for (int p = 1; p < 4; p++) xp[p * 128 + u] *= g1;
    #pragma unroll
    for (int p = 4; p < 9; p++) xp[p * 128 + u] *= g2;
}

__global__ void k_mt(const float* __restrict__ ea, const float* __restrict__ W1, int E) {
    int idx = blockIdx.x * blockDim.x + threadIdx.x;
    if (idx >= E * 8) return;
    int e = idx >> 3, j = idx & 7;
    const float* a = ea + (size_t)e * 64;
    float acc = 0.0f;
    #pragma unroll 16
    for (int i = 0; i < 64; i++) acc += a[i] * W1[i * 8 + j];
    g_mt[idx] = ssp_f(acc * 0.125f);
}

__global__ void k_we(const float* __restrict__ W2, int E) {
    int idx = blockIdx.x * blockDim.x + threadIdx.x;
    if (idx >= E * MUL) return;
    int e = idx >> 7, n = idx & 127;
    const float* m = g_mt + (size_t)e * 8;
    float acc = 0.0f;
    #pragma unroll
    for (int j = 0; j < 8; j++) acc += m[j] * W2[j * MUL + n];
    g_we[idx] = acc * 0.35355339059327373f;
}

// f0' only (np recomputed later in G5)
__global__ void k_f0(const int* __restrict__ dst, const int* __restrict__ src, int E) {
    int idx = blockIdx.x * blockDim.x + threadIdx.x;
    if (idx >= E * MUL) return;
    int e = idx >> 7, u = idx & 127;
    const float* ns = g_na + (size_t)src[e] * TOT;
    const float* nd = g_na + (size_t)dst[e] * TOT;
    const float* w = g_w + (size_t)e * MUL;
    float np[9];
    np[0] = (ns[u] + nd[u]) * w[u / 9];
    #pragma unroll
    for (int p = 1; p < 4; p++) {
        int j = 128 + u * 3 + (p - 1);
        np[p] = (ns[p * 128 + u] + nd[p * 128 + u]) * w[j / 9];
    }
    #pragma unroll
    for (int p = 4; p < 9; p++) {
        int j = 512 + u * 5 + (p - 4);
        np[p] = (ns[p * 128 + u] + nd[p * 128 + u]) * w[j / 9];
    }
    float* f = g_s0f + (size_t)e * NM;
    f[u] = np[0];
    f[128 + u] = sqrtf(np[1] * np[1] + np[2] * np[2] + np[3] * np[3]);
    f[256 + u] = sqrtf(np[4] * np[4] + np[5] * np[5] + np[6] * np[6]
                     + np[7] * np[7] + np[8] * np[8]);
}

// merge planar G5 output + npa -> d_out (coalesced)
__global__ void k_out(const float* __restrict__ npa, float* __restrict__ out, int E) {
    int idx = blockIdx.x * blockDim.x + threadIdx.x;
    if (idx >= E * (TOT / 4)) return;
    int e = idx / (TOT / 4);
    int j4 = (idx - e * (TOT / 4)) * 4;
    const float* pl = g_np + (size_t)e * TOT;
    float4 npv = *(const float4*)(npa + (size_t)e * TOT + j4);
    float4 o;
    o.x = pl[merged_to_planar(j4)]     + npv.x;
    o.y = pl[merged_to_planar(j4 + 1)] + npv.y;
    o.z = pl[merged_to_planar(j4 + 2)] + npv.z;
    o.w = pl[merged_to_planar(j4 + 3)] + npv.w;
    *(float4*)(out + (size_t)e * TOT + j4) = o;
}

// ---------------- mma.sync GEMM ----------------
// CTA: 128 rows x 128 cols, K chunks of 64. 8 warps (4x2), warp tile 32x64.
// split-bf16: D = AhiBhi + AhiBlo + AloBhi. 65KB smem, 2 CTAs/SM.
#define GT 256
#define SM_AHI 0
#define SM_ALO 16384
#define SM_BHI 32768
#define SM_BLO 49152
#define SM_IDX 65536
#define SM_TOTAL 66560

// mode_a: 0 plain A[r*lda + kc*64+k], colblock=by
//         1 G5: recompute np*gate (plane=by); A=g_na table, mul=g_w, gate=g_g
//         2 planar plain (plane=by)
//         3 G1: s0 on the fly from A=g_na0 table (gathers)
// mode_ep: 0 +bias ; 1 silu(+bias) ; 2 (acc+bias)*mul ; 4 planar *S128 (+bias if plane0)
__global__ void __launch_bounds__(GT, 2) gemm_kernel(
    const float* __restrict__ A, int lda, int kchunks,
    const __nv_bfloat16* __restrict__ Bhi, const __nv_bfloat16* __restrict__ Blo,
    float* __restrict__ OUT, int ldo,
    const float* __restrict__ bias,
    const float* __restrict__ mul,
    const float* __restrict__ gate,
    const int* __restrict__ dstp, const int* __restrict__ srcp,
    int mode_a, int mode_ep, int E)
{
    extern __shared__ char smg[];
    uint32_t smb = smem_to_u32(smg);
    int* SIDX = (int*)(smg + SM_IDX);
    const int tid = threadIdx.x;
    const int wid = tid >> 5;
    const int lane = tid & 31;
    const int m0 = blockIdx.x * 128;
    const int by = blockIdx.y;
    const int plane = (mode_a == 1 || mode_a == 2) ? by : 0;
    const int ntb = (mode_a == 1 || mode_a == 2) ? 0 : by;

    const int wm0 = (wid & 3) * 32;
    const int wn0 = (wid >> 2) * 64;

    if (mode_a == 1 || mode_a == 3) {
        if (tid < 128) {
            int e = m0 + tid; if (e >= E) e = E - 1;
            SIDX[tid] = dstp[e];
            SIDX[128 + tid] = srcp[e];
        }
        __syncthreads();
    }

    float acc[2][8][4];
    #pragma unroll
    for (int i = 0; i < 2; i++)
        #pragma unroll
        for (int j = 0; j < 8; j++)
            #pragma unroll
            for (int q = 0; q < 4; q++) acc[i][j][q] = 0.0f;

    int bsel = 0;
    if (mode_a == 1 || mode_a == 2) bsel = (plane == 0) ? 0 : (plane < 4 ? 1 : 2);

    for (int kc = 0; kc < kchunks; kc++) {
        // B tile via cp.async
        {
            int blk = (mode_a == 1 || mode_a == 2) ? (bsel * kchunks + kc) : (ntb * kchunks + kc);
            const char* sH = (const char*)(Bhi + (size_t)blk * BLK);
            const char* sL = (const char*)(Blo + (size_t)blk * BLK);
            for (int i = tid; i < 1024; i += GT) {
                cp_async16(smb + SM_BHI + i * 16, sH + i * 16);
                cp_async16(smb + SM_BLO + i * 16, sL + i * 16);
            }
            CP_COMMIT();
        }
        // A tile: 1024 16B-units
        for (int i = tid; i < 1024; i += GT) {
            int r = i >> 3, u = i & 7;
            int e = m0 + r;
            int k0 = u * 8;
            float v[8];
            #pragma unroll
            for (int q = 0; q < 8; q++) v[q] = 0.0f;
            if (e < E) {
                if (mode_a == 0) {
                    const float* p = A + (size_t)e * lda + kc * 64 + k0;
                    float4 v0 = *(const float4*)(p);
                    float4 v1 = *(const float4*)(p + 4);
                    v[0]=v0.x; v[1]=v0.y; v[2]=v0.z; v[3]=v0.w;
                    v[4]=v1.x; v[5]=v1.y; v[6]=v1.z; v[7]=v1.w;
                } else if (mode_a == 2) {
                    const float* p = A + (size_t)e * lda + plane * 128 + kc * 64 + k0;
                    float4 v0 = *(const float4*)(p);
                    float4 v1 = *(const float4*)(p + 4);
                    v[0]=v0.x; v[1]=v0.y; v[2]=v0.z; v[3]=v0.w;
                    v[4]=v1.x; v[5]=v1.y; v[6]=v1.z; v[7]=v1.w;
                } else if (mode_a == 1) {
                    if (plane == 0) {
                        const float* p = gate + (size_t)e * NM + kc * 64 + k0;
                        float4 v0 = *(const float4*)(p);
                        float4 v1 = *(const float4*)(p + 4);
                        v[0]=v0.x; v[1]=v0.y; v[2]=v0.z; v[3]=v0.w;
                        v[4]=v1.x; v[5]=v1.y; v[6]=v1.z; v[7]=v1.w;
                    } else {
                        const float* nd = A + (size_t)SIDX[r] * TOT + plane * 128 + kc * 64 + k0;
                        const float* ns = A + (size_t)SIDX[128 + r] * TOT + plane * 128 + kc * 64 + k0;
                        int go = (plane < 4) ? 128 : 256;
                        const float* gp = gate + (size_t)e * NM + go + kc * 64 + k0;
                        const float* wr = mul + (size_t)e * MUL;
                        #pragma unroll
                        for (int q = 0; q < 8; q++) {
                            int k = kc * 64 + k0 + q;
                            int j = (plane < 4) ? (128 + k * 3 + (plane - 1))
                                                : (512 + k * 5 + (plane - 4));
                            v[q] = (nd[q] + ns[q]) * wr[j / 9] * gp[q];
                        }
                    }
                } else { // mode_a == 3: s0 from g_na0 gathers
                    const float* nd = A + (size_t)SIDX[r] * TOT;
                    const float* ns = A + (size_t)SIDX[128 + r] * TOT;
                    int kg = kc * 64 + k0;
                    if (kg < 128) {
                        #pragma unroll
                        for (int q = 0; q < 8; q++)
                            v[q] = 0.5f * (nd[kg + q] + ns[kg + q]);
                    } else if (kg < 256) {
                        int u0 = kg - 128;
                        #pragma unroll
                        for (int q = 0; q < 8; q++) {
                            int uu = u0 + q;
                            v[q] = (nd[128 + uu] * ns[128 + uu] + nd[256 + uu] * ns[256 + uu]
                                  + nd[384 + uu] * ns[384 + uu]) * IS3;
                        }
                    } else {
                        int u0 = kg - 256;
                        #pragma unroll
                        for (int q = 0; q < 8; q++) {
                            int uu = u0 + q;
                            v[q] = (nd[512 + uu] * ns[512 + uu] + nd[640 + uu] * ns[640 + uu]
                                  + nd[768 + uu] * ns[768 + uu] + nd[896 + uu] * ns[896 + uu]
                                  + nd[1024 + uu] * ns[1024 + uu]) * IS5;
                        }
                    }
                }
            }
            uint32_t hi[4], lo[4];
            #pragma unroll
            for (int q = 0; q < 4; q++) {
                __nv_bfloat16 h0 = __float2bfloat16(v[2*q]);
                __nv_bfloat16 h1 = __float2bfloat16(v[2*q+1]);
                __nv_bfloat16 l0 = __float2bfloat16(v[2*q]   - __bfloat162float(h0));
                __nv_bfloat16 l1 = __float2bfloat16(v[2*q+1] - __bfloat162float(h1));
                __nv_bfloat162 h2(h0, h1), l2(l0, l1);
                hi[q] = *(uint32_t*)&h2;
                lo[q] = *(uint32_t*)&l2;
            }
            int off = sw_unit(r, u) * 16;
            *(uint4*)(smg + SM_AHI + off) = make_uint4(hi[0], hi[1], hi[2], hi[3]);
            *(uint4*)(smg + SM_ALO + off) = make_uint4(lo[0], lo[1], lo[2], lo[3]);
        }
        CP_WAIT0();
        __syncthreads();

        #pragma unroll
        for (int pass = 0; pass < 3; pass++) {
            uint32_t Abase = smb + ((pass == 2) ? SM_ALO : SM_AHI);
            uint32_t Bbase = smb + ((pass == 1) ? SM_BLO : SM_BHI);
            #pragma unroll
            for (int ks = 0; ks < 4; ks++) {
                uint32_t a[2][4];
                #pragma unroll
                for (int mt = 0; mt < 2; mt++) {
                    int row = wm0 + mt * 16 + (lane & 15);
                    int u = ks * 2 + (lane >> 4);
                    ldmat_x4(a[mt], Abase + sw_unit(row, u) * 16);
                }
                uint32_t b[4][4];
                #pragma unroll
                for (int nq = 0; nq < 4; nq++) {
                    int n = wn0 + nq * 16 + (lane >> 4) * 8 + (lane & 7);
                    int u = ks * 2 + ((lane >> 3) & 1);
                    ldmat_x4(b[nq], Bbase + sw_unit(n, u) * 16);
                }
                #pragma unroll
                for (int mt = 0; mt < 2; mt++)
                    #pragma unroll
                    for (int nt = 0; nt < 8; nt++)
                        mma_bf16(acc[mt][nt], a[mt], b[nt >> 1][(nt & 1) * 2],
                                 b[nt >> 1][(nt & 1) * 2 + 1]);
            }
        }
        __syncthreads();
    }

    // ---------------- epilogue ----------------
    const int qr = lane >> 2;
    const int qc = (lane & 3) * 2;
    #pragma unroll
    for (int mt = 0; mt < 2; mt++) {
        #pragma unroll
        for (int nt = 0; nt < 8; nt++) {
            int cl = wn0 + nt * 8 + qc;
            float* c = acc[mt][nt];
            #pragma unroll
            for (int rr = 0; rr < 2; rr++) {
                int e = m0 + wm0 + mt * 16 + qr + rr * 8;
                if (e >= E) continue;
                float v0 = c[rr * 2], v1 = c[rr * 2 + 1];
                if (mode_ep == 4) {
                    v0 *= S128; v1 *= S128;
                    if (plane == 0 && bias) { v0 += bias[cl]; v1 += bias[cl + 1]; }
                    int n = plane * 128 + cl;
                    OUT[(size_t)e * ldo + n]     = v0;
                    OUT[(size_t)e * ldo + n + 1] = v1;
                } else {
                    int n = ntb * 128 + cl;
                    if (bias) { v0 += bias[n]; v1 += bias[n + 1]; }
                    if (mode_ep == 1) { v0 = silu_f(v0); v1 = silu_f(v1); }
                    else if (mode_ep == 2) {
                        v0 *= mul[(size_t)e * MUL + cl];
                        v1 *= mul[(size_t)e * MUL + cl + 1];
                    }
                    OUT[(size_t)e * ldo + n]     = v0;
                    OUT[(size_t)e * ldo + n + 1] = v1;
                }
            }
        }
    }
}

// ---------------- launch ----------------
extern "C" void kernel_launch(void* const* d_in, const int* in_sizes, int n_in,
                              void* d_out, int out_size) {
    const float* node_attr = (const float*)d_in[0];
    const float* edge_attr = (const float*)d_in[1];
    const int*   dst       = (const int*)d_in[2];
    const int*   src       = (const int*)d_in[3];
    const float* npa       = (const float*)d_in[4];
    const float* W_inner   = (const float*)d_in[5];
    const float* b_inner   = (const float*)d_in[6];
    const float* W_n       = (const float*)d_in[7];
    const float* b_n       = (const float*)d_in[8];
    const float* W_out     = (const float*)d_in[9];
    const float* b_out     = (const float*)d_in[10];
    const float* pW1       = (const float*)d_in[11];
    const float* pb1       = (const float*)d_in[12];
    const float* pW2       = (const float*)d_in[13];
    const float* pb2       = (const float*)d_in[14];
    const float* gW1       = (const float*)d_in[15];
    const float* gb1       = (const float*)d_in[16];
    const float* gW2       = (const float*)d_in[17];
    const float* gb2       = (const float*)d_in[18];
    const float* fcEW1     = (const float*)d_in[19];
    const float* fcEW2     = (const float*)d_in[20];
    const float* fcW1      = (const float*)d_in[21];
    const float* fcb1      = (const float*)d_in[22];
    const float* fcW2      = (const float*)d_in[23];
    const float* fcb2      = (const float*)d_in[24];

    int N = in_sizes[0] / TOT;
    int E = in_sizes[2];
    int mt = (E + 127) / 128;
    int nt = (N + 127) / 128;

    void *p_s0f, *p_h, *p_w, *p_np, *p_g, *p_we, *p_pwhi, *p_pwlo;
    void *p_xp, *p_nf, *p_nh, *p_ng, *p_na0, *p_na;
    cudaGetSymbolAddress(&p_s0f, g_s0f);
    cudaGetSymbolAddress(&p_h,   g_h);
    cudaGetSymbolAddress(&p_w,   g_w);
    cudaGetSymbolAddress(&p_np,  g_np);
    cudaGetSymbolAddress(&p_g,   g_g);
    cudaGetSymbolAddress(&p_we,  g_we);
    cudaGetSymbolAddress(&p_pwhi, g_pw_hi);
    cudaGetSymbolAddress(&p_pwlo, g_pw_lo);
    cudaGetSymbolAddress(&p_xp,  g_xp);
    cudaGetSymbolAddress(&p_nf,  g_nf);
    cudaGetSymbolAddress(&p_nh,  g_nh);
    cudaGetSymbolAddress(&p_ng,  g_ng);
    cudaGetSymbolAddress(&p_na0, g_na0);
    cudaGetSymbolAddress(&p_na,  g_na);
    const __nv_bfloat16* pwhi = (const __nv_bfloat16*)p_pwhi;
    const __nv_bfloat16* pwlo = (const __nv_bfloat16*)p_pwlo;

    cudaFuncSetAttribute(gemm_kernel, cudaFuncAttributeMaxDynamicSharedMemorySize, SM_TOTAL);

    // ---- weight prep ----
    prep_weight<<<(NM * MUL + 255) / 256, 256>>>(fcW1, NM, MUL, OFF_FCW1);
    prep_weight<<<(MUL * MUL + 255) / 256, 256>>>(fcW2, MUL, MUL, OFF_FCW2);
    prep_weight<<<(NM * NM + 255) / 256, 256>>>(gW1, NM, NM, OFF_NGW1);
    prep_weight<<<(NM * NM + 255) / 256, 256>>>(gW2, NM, NM, OFF_NGW2);
    prep_weight<<<(NM * NM + 255) / 256, 256>>>(pW1, NM, NM, OFF_PW1);
    prep_weight<<<(NM * NM + 255) / 256, 256>>>(pW2, NM, NM, OFF_PW2);
    for (int i = 0; i < 3; i++) {
        prep_weight<<<(MUL * MUL + 255) / 256, 256>>>(W_out + i * MUL * MUL, MUL, MUL,
                                                      OFF_WOUT + i * 2 * BLK);
        prep_weight<<<(MUL * MUL + 255) / 256, 256>>>(W_inner + i * MUL * MUL, MUL, MUL,
                                                      OFF_WIN + i * 2 * BLK);
        prep_weight<<<(MUL * MUL + 255) / 256, 256>>>(W_n + i * MUL * MUL, MUL, MUL,
                                                      OFF_WN + i * 2 * BLK);
    }

    // ---- node stage ----
    k_xplan<<<(N * MUL + 255) / 256, 256>>>(node_attr, N);

    gemm_kernel<<<dim3(nt, 9), GT, SM_TOTAL>>>(
        (const float*)p_xp, TOT, 2, pwhi + OFF_WIN, pwlo + OFF_WIN,
        (float*)p_na0, TOT, b_inner, nullptr, nullptr, nullptr, nullptr, 2, 4, N);

    gemm_kernel<<<dim3(nt, 3), GT, SM_TOTAL>>>(
        (const float*)p_nf, NM, 6, pwhi + OFF_PW1, pwlo + OFF_PW1,
        (float*)p_nh, NM, pb1, nullptr, nullptr, nullptr, nullptr, 0, 1, N);

    gemm_kernel<<<dim3(nt, 3), GT, SM_TOTAL>>>(
        (const float*)p_nh, NM, 6, pwhi + OFF_PW2, pwlo + OFF_PW2,
        (float*)p_ng, NM, pb2, nullptr, nullptr, nullptr, nullptr, 0, 0, N);

    k_gate_node<<<(N * MUL + 255) / 256, 256>>>(N);

    gemm_kernel<<<dim3(nt, 9), GT, SM_TOTAL>>>(
        (const float*)p_xp, TOT, 2, pwhi + OFF_WN, pwlo + OFF_WN,
        (float*)p_na, TOT, b_n, nullptr, nullptr, nullptr, nullptr, 2, 4, N);

    // ---- edge stage ----
    k_mt<<<(E * 8 + 255) / 256, 256>>>(edge_attr, fcEW1, E);
    k_we<<<(E * MUL + 255) / 256, 256>>>(fcEW2, E);

    // G1: h1 = silu(s0 @ fcW1 + fcb1), s0 computed in A-load from g_na0
    gemm_kernel<<<dim3(mt, 1), GT, SM_TOTAL>>>(
        (const float*)p_na0, TOT, 6, pwhi + OFF_FCW1, pwlo + OFF_FCW1,
        (float*)p_h, MUL, fcb1, nullptr, nullptr, dst, src, 3, 1, E);

    // G2: w = (h1 @ fcW2 + fcb2) * we
    gemm_kernel<<<dim3(mt, 1), GT, SM_TOTAL>>>(
        (const float*)p_h, MUL, 2, pwhi + OFF_FCW2, pwlo + OFF_FCW2,
        (float*)p_w, MUL, fcb2, (const float*)p_we, nullptr, nullptr, nullptr, 0, 2, E);

    // f0'
    k_f0<<<(E * MUL + 255) / 256, 256>>>(dst, src, E);

    // G3: h = silu(f0' @ ngW1 + ngb1)
    gemm_kernel<<<dim3(mt, 3), GT, SM_TOTAL>>>(
        (const float*)p_s0f, NM, 6, pwhi + OFF_NGW1, pwlo + OFF_NGW1,
        (float*)p_h, NM, gb1, nullptr, nullptr, nullptr, nullptr, 0, 1, E);

    // G4: g = h @ ngW2 + ngb2
    gemm_kernel<<<dim3(mt, 3), GT, SM_TOTAL>>>(
        (const float*)p_h, NM, 6, pwhi + OFF_NGW2, pwlo + OFF_NGW2,
        (float*)p_g, NM, gb2, nullptr, nullptr, nullptr, nullptr, 0, 0, E);

    // G5: planar out = irrep(gate(np, g), W_out)*S128 (+bias plane0); np recomputed
    gemm_kernel<<<dim3(mt, 9), GT, SM_TOTAL>>>(
        (const float*)p_na, TOT, 2, pwhi + OFF_WOUT, pwlo + OFF_WOUT,
        (float*)p_np, TOT, b_out, (const float*)p_w, (const float*)p_g, dst, src, 1, 4, E);

    // merge + npa
    k_out<<<(E * (TOT / 4) + 255) / 256, 256>>>(npa, (float*)d_out, E);
}